// round 2
// baseline (speedup 1.0000x reference)
#include <cuda_runtime.h>
#include <math.h>
#include <float.h>

// Problem constants (fixed shapes from reference setup_inputs)
#define NIMG 2
#define MBOX 1000
#define NBOX (NIMG*MBOX)
#define CCH  256
#define RR   7
#define FCIN (CCH*RR*RR)      // 12544
#define FCD  1024
#define SORT_N 1024
#define NWORDS 16             // ceil(1000/64)
#define SCORE_THRESH 0.05f
#define NMS_THRESH 0.5f
#define TOPK 100
#define SCALE_CLAMP 4.135166556742356f  // log(1000/16)

// ---------------- scratch (device globals; no allocations allowed) ----------
__device__ float g_X [NBOX * FCIN];   // pooled features, row-major (2000 x 12544)
__device__ float g_Y1[NBOX * FCD];
__device__ float g_Y2[NBOX * FCD];
__device__ float g_scores[NBOX];
__device__ float g_pboxes[NBOX * 4];  // clipped predicted boxes
__device__ unsigned long long g_sup[NIMG * MBOX * NWORDS];

// ---------------- pooling (ROIAlign-nearest per reference) ------------------
__global__ void pool_kernel(const float* __restrict__ p2, const float* __restrict__ p3,
                            const float* __restrict__ p4, const float* __restrict__ p5,
                            const float* __restrict__ props)
{
    int box = blockIdx.x;           // 0..1999
    int img = box / MBOX;

    __shared__ int six[RR], siy[RR];
    __shared__ const float* sbase;
    __shared__ int sW, sHW;

    if (threadIdx.x == 0) {
        const float* fmaps[4] = {p2, p3, p4, p5};
        const int   Hs[4] = {200, 100, 50, 25};
        const int   Ws[4] = {304, 152, 76, 38};
        const float sc4[4] = {0.25f, 0.125f, 0.0625f, 0.03125f};

        const float* pr = props + (size_t)box * 4;
        float x1o = pr[0], y1o = pr[1], x2o = pr[2], y2o = pr[3];

        // level assignment — mirror JAX op order exactly (no contraction risk:
        // all distinct rounded ops)
        float w = __fsub_rn(x2o, x1o);
        float h = __fsub_rn(y2o, y1o);
        float s = sqrtf(fmaxf(__fmul_rn(w, h), 1e-6f));
        float lv = floorf(__fadd_rn(4.0f, log2f(__fadd_rn(__fdiv_rn(s, 224.0f), 1e-8f))));
        lv = fminf(fmaxf(lv, 2.0f), 5.0f);
        int lvl = (int)lv - 2;      // 0..3

        float sc = sc4[lvl];        // powers of two: multiply is exact
        float x1 = __fmul_rn(x1o, sc), y1 = __fmul_rn(y1o, sc);
        float x2 = __fmul_rn(x2o, sc), y2 = __fmul_rn(y2o, sc);
        float bw = __fdiv_rn(fmaxf(__fsub_rn(x2, x1), 1.0f), 7.0f);
        float bh = __fdiv_rn(fmaxf(__fsub_rn(y2, y1), 1.0f), 7.0f);
        int Wl = Ws[lvl], Hl = Hs[lvl];
        for (int j = 0; j < RR; j++) {
            // JAX: gx = x1 + cs*bw  (mul rounded, then add rounded — NO fma)
            float cs = (float)j + 0.5f;
            float gx = __fadd_rn(x1, __fmul_rn(cs, bw));
            float gy = __fadd_rn(y1, __fmul_rn(cs, bh));
            int ix = (int)gx;                 // trunc toward zero, same as astype(int32)
            int iy = (int)gy;
            six[j] = min(max(ix, 0), Wl - 1);
            siy[j] = min(max(iy, 0), Hl - 1);
        }
        sbase = fmaps[lvl] + (size_t)img * CCH * Hl * Wl;
        sW = Wl;
        sHW = Hl * Wl;
    }
    __syncthreads();

    const float* base = sbase;
    int Wl = sW, HW = sHW;
    float* out = g_X + (size_t)box * FCIN;
    for (int t = threadIdx.x; t < FCIN; t += blockDim.x) {
        int c = t / 49;
        int p = t % 49;
        int gy = p / 7, gx = p % 7;
        out[t] = base[(size_t)c * HW + siy[gy] * Wl + six[gx]];
    }
}

// ---------------- fp32 SGEMM with Kahan accumulation: C = relu(A @ B + bias) -
// A: Mrows x Kdim row-major; B: Kdim x Ndim row-major. Ndim%128==0, Kdim%8==0.
// Kahan compensation implemented with explicit-rounding intrinsics so no
// compiler flag can fuse/reassociate it away.
template<bool RELU>
__global__ void __launch_bounds__(256) sgemm_kernel(
    const float* __restrict__ A, const float* __restrict__ B,
    const float* __restrict__ bias, float* __restrict__ Cmat,
    int Mrows, int Kdim, int Ndim)
{
    const int BM = 128, BN = 128, BK = 8;
    __shared__ float As[BK][BM];
    __shared__ float Bs[BK][BN];

    int tid = threadIdx.x;
    int bm = blockIdx.y * BM, bn = blockIdx.x * BN;
    int ty = tid / 16, tx = tid % 16;

    float acc[8][8];
    float cmp[8][8];
    #pragma unroll
    for (int i = 0; i < 8; i++)
        #pragma unroll
        for (int j = 0; j < 8; j++) { acc[i][j] = 0.0f; cmp[i][j] = 0.0f; }

    int a_row = tid >> 1;          // 0..127
    int a_k   = (tid & 1) * 4;     // 0 or 4
    int b_k   = tid >> 5;          // 0..7
    int b_n   = (tid & 31) * 4;

    for (int k0 = 0; k0 < Kdim; k0 += BK) {
        float4 av;
        int gr = bm + a_row;
        if (gr < Mrows) av = *(const float4*)(A + (size_t)gr * Kdim + k0 + a_k);
        else            av = make_float4(0.f, 0.f, 0.f, 0.f);
        As[a_k + 0][a_row] = av.x;
        As[a_k + 1][a_row] = av.y;
        As[a_k + 2][a_row] = av.z;
        As[a_k + 3][a_row] = av.w;

        float4 bv = *(const float4*)(B + (size_t)(k0 + b_k) * Ndim + bn + b_n);
        *(float4*)&Bs[b_k][b_n] = bv;
        __syncthreads();

        #pragma unroll
        for (int k = 0; k < BK; k++) {
            float ar[8], br[8];
            #pragma unroll
            for (int i = 0; i < 8; i++) ar[i] = As[k][ty * 8 + i];
            #pragma unroll
            for (int j = 0; j < 8; j++) br[j] = Bs[k][tx * 8 + j];
            #pragma unroll
            for (int i = 0; i < 8; i++) {
                #pragma unroll
                for (int j = 0; j < 8; j++) {
                    // y = a*b - cmp (fused); Kahan add into acc
                    float y = __fmaf_rn(ar[i], br[j], -cmp[i][j]);
                    float t = __fadd_rn(acc[i][j], y);
                    cmp[i][j] = __fsub_rn(__fsub_rn(t, acc[i][j]), y);
                    acc[i][j] = t;
                }
            }
        }
        __syncthreads();
    }

    #pragma unroll
    for (int i = 0; i < 8; i++) {
        int r = bm + ty * 8 + i;
        if (r >= Mrows) continue;
        #pragma unroll
        for (int j = 0; j < 8; j++) {
            int ccol = bn + tx * 8 + j;
            float v = __fadd_rn(acc[i][j], bias[ccol]);
            if (RELU) v = fmaxf(v, 0.0f);
            Cmat[(size_t)r * Ndim + ccol] = v;
        }
    }
}

// ---------------- heads: cls/box projections + softmax + deltas + clip ------
// fp64 accumulation for the 6 small dots (exact ordering-insensitive logits).
__global__ void heads_kernel(const float* __restrict__ Y2,
                             const float* __restrict__ Wc, const float* __restrict__ bc,
                             const float* __restrict__ Wb, const float* __restrict__ bb,
                             const float* __restrict__ props,
                             const int* __restrict__ isz,
                             float* __restrict__ scores, float* __restrict__ pboxes)
{
    int box = blockIdx.x;
    const float* x = Y2 + (size_t)box * FCD;

    double a0 = 0., a1 = 0., a2 = 0., a3 = 0., a4 = 0., a5 = 0.;
    for (int k = threadIdx.x; k < FCD; k += blockDim.x) {
        double xv = (double)x[k];
        a0 += xv * (double)Wc[k * 2 + 0];
        a1 += xv * (double)Wc[k * 2 + 1];
        a2 += xv * (double)Wb[k * 4 + 0];
        a3 += xv * (double)Wb[k * 4 + 1];
        a4 += xv * (double)Wb[k * 4 + 2];
        a5 += xv * (double)Wb[k * 4 + 3];
    }
    __shared__ double red[6][128];
    red[0][threadIdx.x] = a0; red[1][threadIdx.x] = a1; red[2][threadIdx.x] = a2;
    red[3][threadIdx.x] = a3; red[4][threadIdx.x] = a4; red[5][threadIdx.x] = a5;
    __syncthreads();
    for (int s = 64; s > 0; s >>= 1) {
        if (threadIdx.x < s)
            #pragma unroll
            for (int j = 0; j < 6; j++)
                red[j][threadIdx.x] += red[j][threadIdx.x + s];
        __syncthreads();
    }
    if (threadIdx.x == 0) {
        float l0 = (float)(red[0][0] + (double)bc[0]);
        float l1 = (float)(red[1][0] + (double)bc[1]);
        float m = fmaxf(l0, l1);
        float e0 = expf(__fsub_rn(l0, m)), e1 = expf(__fsub_rn(l1, m));
        scores[box] = __fdiv_rn(e1, __fadd_rn(e0, e1));

        float dx = (float)(red[2][0] + (double)bb[0]);
        float dy = (float)(red[3][0] + (double)bb[1]);
        float dw = fminf((float)(red[4][0] + (double)bb[2]), SCALE_CLAMP);
        float dh = fminf((float)(red[5][0] + (double)bb[3]), SCALE_CLAMP);

        const float* pr = props + (size_t)box * 4;
        float w = __fsub_rn(pr[2], pr[0]), h = __fsub_rn(pr[3], pr[1]);
        float cx = __fadd_rn(pr[0], __fmul_rn(0.5f, w));
        float cy = __fadd_rn(pr[1], __fmul_rn(0.5f, h));
        float pcx = __fadd_rn(__fmul_rn(dx, w), cx);
        float pcy = __fadd_rn(__fmul_rn(dy, h), cy);
        float pw = __fmul_rn(expf(dw), w);
        float ph = __fmul_rn(expf(dh), h);

        int img = box / MBOX;
        float Hh = (float)isz[img * 2 + 0];
        float Ww = (float)isz[img * 2 + 1];
        float bx1 = fminf(fmaxf(__fsub_rn(pcx, __fmul_rn(0.5f, pw)), 0.f), Ww);
        float by1 = fminf(fmaxf(__fsub_rn(pcy, __fmul_rn(0.5f, ph)), 0.f), Hh);
        float bx2 = fminf(fmaxf(__fadd_rn(pcx, __fmul_rn(0.5f, pw)), 0.f), Ww);
        float by2 = fminf(fmaxf(__fadd_rn(pcy, __fmul_rn(0.5f, ph)), 0.f), Hh);
        pboxes[box * 4 + 0] = bx1;
        pboxes[box * 4 + 1] = by1;
        pboxes[box * 4 + 2] = bx2;
        pboxes[box * 4 + 3] = by2;
    }
}

// ---------------- per-image stable sort + NMS + topk + write outputs --------
__global__ void __launch_bounds__(512) sortnms_kernel(
    const float* __restrict__ scores, const float* __restrict__ pboxes,
    float* __restrict__ out)
{
    int img = blockIdx.x;
    int tid = threadIdx.x;

    __shared__ float key[SORT_N];
    __shared__ int   idx[SORT_N];
    __shared__ float4 sb[MBOX];
    __shared__ float  sarea[MBOX];
    __shared__ unsigned long long keepw[NWORDS];

    for (int i = tid; i < SORT_N; i += 512) {
        if (i < MBOX) { key[i] = scores[img * MBOX + i]; idx[i] = i; }
        else          { key[i] = -FLT_MAX;               idx[i] = i; }
    }
    __syncthreads();

    // bitonic sort: descending score, tie-break ascending index (stable argsort)
    for (int k = 2; k <= SORT_N; k <<= 1) {
        for (int j = k >> 1; j > 0; j >>= 1) {
            for (int i = tid; i < SORT_N; i += 512) {
                int ixj = i ^ j;
                if (ixj > i) {
                    float ka = key[i], kb = key[ixj];
                    int ia = idx[i], ib = idx[ixj];
                    bool a_before_b = (ka > kb) || (ka == kb && ia < ib);
                    bool up = ((i & k) == 0);
                    bool sw = up ? !a_before_b : a_before_b;
                    if (sw) { key[i] = kb; key[ixj] = ka; idx[i] = ib; idx[ixj] = ia; }
                }
            }
            __syncthreads();
        }
    }

    // gather sorted boxes (already clipped)
    for (int i = tid; i < MBOX; i += 512) {
        const float* p = pboxes + (size_t)(img * MBOX + idx[i]) * 4;
        float4 b = make_float4(p[0], p[1], p[2], p[3]);
        sb[i] = b;
        sarea[i] = (b.z - b.x) * (b.w - b.y);
    }
    __syncthreads();

    // suppression bitmask: sup[i][w] bit jj set iff iou(i, w*64+jj) > T and j > i
    unsigned long long* sup = g_sup + (size_t)img * MBOX * NWORDS;
    for (int t = tid; t < MBOX * NWORDS; t += 512) {
        int i = t / NWORDS, w = t % NWORDS;
        float4 a = sb[i];
        float aa = sarea[i];
        unsigned long long m = 0ull;
        int j0 = w * 64;
        int jend = min(j0 + 64, MBOX);
        for (int j = max(j0, i + 1); j < jend; j++) {
            float4 b = sb[j];
            float lx = fmaxf(a.x, b.x), ly = fmaxf(a.y, b.y);
            float rx = fminf(a.z, b.z), ry = fminf(a.w, b.w);
            float iw = fmaxf(rx - lx, 0.f), ih = fmaxf(ry - ly, 0.f);
            float inter = iw * ih;
            float iou = inter / fmaxf(aa + sarea[j] - inter, 1e-9f);
            if (iou > NMS_THRESH) m |= 1ull << (j - j0);
        }
        sup[t] = m;
    }
    if (tid < NWORDS) {
        unsigned long long m = 0ull;
        for (int jj = 0; jj < 64; jj++) {
            int j = tid * 64 + jj;
            if (j < MBOX && key[j] > SCORE_THRESH) m |= 1ull << jj;
        }
        keepw[tid] = m;
    }
    __syncthreads();

    // sequential NMS scan (warp 0)
    if (tid < 32) {
        volatile unsigned long long* kw = keepw;
        for (int i = 0; i < MBOX; i++) {
            unsigned long long kwi = kw[i >> 6];
            __syncwarp();
            if ((kwi >> (i & 63)) & 1ull) {
                if (tid < NWORDS)
                    kw[tid] = kw[tid] & ~sup[(size_t)i * NWORDS + tid];
            }
            __syncwarp();
        }
        if (tid == 0) {
            int cnt = 0;
            for (int i = 0; i < MBOX; i++) {
                int w = i >> 6, b = i & 63;
                if ((kw[w] >> b) & 1ull) {
                    cnt++;
                    if (cnt > TOPK) kw[w] = kw[w] & ~(1ull << b);
                }
            }
        }
    }
    __syncthreads();

    // outputs: [boxes | scores | keep | order] all as float
    float* oB = out;
    float* oS = out + (size_t)NIMG * MBOX * 4;
    float* oK = oS + (size_t)NIMG * MBOX;
    float* oO = oK + (size_t)NIMG * MBOX;
    for (int i = tid; i < MBOX; i += 512) {
        float4 b = sb[i];
        size_t o = (size_t)(img * MBOX + i);
        oB[o * 4 + 0] = b.x;
        oB[o * 4 + 1] = b.y;
        oB[o * 4 + 2] = b.z;
        oB[o * 4 + 3] = b.w;
        oS[o] = key[i];
        int w = i >> 6, bb2 = i & 63;
        oK[o] = ((keepw[w] >> bb2) & 1ull) ? 1.0f : 0.0f;
        oO[o] = (float)idx[i];
    }
}

// ---------------- launcher ---------------------------------------------------
extern "C" void kernel_launch(void* const* d_in, const int* in_sizes, int n_in,
                              void* d_out, int out_size)
{
    const float* p2    = (const float*)d_in[0];
    const float* p3    = (const float*)d_in[1];
    const float* p4    = (const float*)d_in[2];
    const float* p5    = (const float*)d_in[3];
    const float* props = (const float*)d_in[4];
    const int*   isz   = (const int*)  d_in[5];
    const float* W1    = (const float*)d_in[6];
    const float* b1    = (const float*)d_in[7];
    const float* W2    = (const float*)d_in[8];
    const float* b2    = (const float*)d_in[9];
    const float* Wc    = (const float*)d_in[10];
    const float* bc    = (const float*)d_in[11];
    const float* Wb    = (const float*)d_in[12];
    const float* bb    = (const float*)d_in[13];
    float* out = (float*)d_out;

    void *pX, *pY1, *pY2, *pSc, *pPb;
    cudaGetSymbolAddress(&pX,  g_X);
    cudaGetSymbolAddress(&pY1, g_Y1);
    cudaGetSymbolAddress(&pY2, g_Y2);
    cudaGetSymbolAddress(&pSc, g_scores);
    cudaGetSymbolAddress(&pPb, g_pboxes);
    float* X  = (float*)pX;
    float* Y1 = (float*)pY1;
    float* Y2 = (float*)pY2;
    float* Sc = (float*)pSc;
    float* Pb = (float*)pPb;

    pool_kernel<<<NBOX, 256>>>(p2, p3, p4, p5, props);

    dim3 g1(FCD / 128, (NBOX + 127) / 128);
    sgemm_kernel<true><<<g1, 256>>>(X, W1, b1, Y1, NBOX, FCIN, FCD);
    sgemm_kernel<true><<<g1, 256>>>(Y1, W2, b2, Y2, NBOX, FCD, FCD);

    heads_kernel<<<NBOX, 128>>>(Y2, Wc, bc, Wb, bb, props, isz, Sc, Pb);

    sortnms_kernel<<<NIMG, 512>>>(Sc, Pb, out);
}

// round 3
// speedup vs baseline: 1.0002x; 1.0002x over previous
#include <cuda_runtime.h>
#include <math.h>
#include <float.h>

// Problem constants (fixed shapes from reference setup_inputs)
#define NIMG 2
#define MBOX 1000
#define NBOX (NIMG*MBOX)
#define CCH  256
#define RR   7
#define FCIN (CCH*RR*RR)      // 12544
#define FCD  1024
#define SORT_N 1024
#define NWORDS 16             // ceil(1000/64)
#define SCORE_THRESH 0.05f
#define NMS_THRESH 0.5f
#define TOPK 100
#define SCALE_CLAMP 4.135166556742356f  // log(1000/16)

typedef unsigned long long ull;

// ---------------- scratch (device globals; no allocations allowed) ----------
__device__ float g_X [NBOX * FCIN];   // pooled features, row-major (2000 x 12544)
__device__ float g_Y1[NBOX * FCD];
__device__ float g_Y2[NBOX * FCD];
__device__ float g_scores[NBOX];
__device__ float g_pboxes[NBOX * 4];  // clipped predicted boxes
__device__ unsigned long long g_sup[NIMG * MBOX * NWORDS];

// ---------------- packed f32x2 helpers (sm_100+) -----------------------------
__device__ __forceinline__ ull ffma2(ull a, ull b, ull c) {
    ull d;
    asm("fma.rn.f32x2 %0, %1, %2, %3;" : "=l"(d) : "l"(a), "l"(b), "l"(c));
    return d;
}
__device__ __forceinline__ ull fadd2(ull a, ull b) {
    ull d;
    asm("add.rn.f32x2 %0, %1, %2;" : "=l"(d) : "l"(a), "l"(b));
    return d;
}
__device__ __forceinline__ ull pack2(float x) {
    ull d;
    unsigned u = __float_as_uint(x);
    asm("mov.b64 %0, {%1, %1};" : "=l"(d) : "r"(u));
    return d;
}
__device__ __forceinline__ float2 unpack2(ull v) {
    unsigned lo, hi;
    asm("mov.b64 {%0, %1}, %2;" : "=r"(lo), "=r"(hi) : "l"(v));
    return make_float2(__uint_as_float(lo), __uint_as_float(hi));
}

// ---------------- pooling (ROIAlign-nearest per reference) ------------------
__global__ void pool_kernel(const float* __restrict__ p2, const float* __restrict__ p3,
                            const float* __restrict__ p4, const float* __restrict__ p5,
                            const float* __restrict__ props)
{
    int box = blockIdx.x;           // 0..1999
    int img = box / MBOX;

    __shared__ int six[RR], siy[RR];
    __shared__ const float* sbase;
    __shared__ int sW, sHW;

    if (threadIdx.x == 0) {
        const float* fmaps[4] = {p2, p3, p4, p5};
        const int   Hs[4] = {200, 100, 50, 25};
        const int   Ws[4] = {304, 152, 76, 38};
        const float sc4[4] = {0.25f, 0.125f, 0.0625f, 0.03125f};

        const float* pr = props + (size_t)box * 4;
        float x1o = pr[0], y1o = pr[1], x2o = pr[2], y2o = pr[3];

        float w = __fsub_rn(x2o, x1o);
        float h = __fsub_rn(y2o, y1o);
        float s = sqrtf(fmaxf(__fmul_rn(w, h), 1e-6f));
        float lv = floorf(__fadd_rn(4.0f, log2f(__fadd_rn(__fdiv_rn(s, 224.0f), 1e-8f))));
        lv = fminf(fmaxf(lv, 2.0f), 5.0f);
        int lvl = (int)lv - 2;      // 0..3

        float sc = sc4[lvl];        // powers of two: multiply is exact
        float x1 = __fmul_rn(x1o, sc), y1 = __fmul_rn(y1o, sc);
        float x2 = __fmul_rn(x2o, sc), y2 = __fmul_rn(y2o, sc);
        float bw = __fdiv_rn(fmaxf(__fsub_rn(x2, x1), 1.0f), 7.0f);
        float bh = __fdiv_rn(fmaxf(__fsub_rn(y2, y1), 1.0f), 7.0f);
        int Wl = Ws[lvl], Hl = Hs[lvl];
        for (int j = 0; j < RR; j++) {
            float cs = (float)j + 0.5f;
            float gx = __fadd_rn(x1, __fmul_rn(cs, bw));
            float gy = __fadd_rn(y1, __fmul_rn(cs, bh));
            int ix = (int)gx;
            int iy = (int)gy;
            six[j] = min(max(ix, 0), Wl - 1);
            siy[j] = min(max(iy, 0), Hl - 1);
        }
        sbase = fmaps[lvl] + (size_t)img * CCH * Hl * Wl;
        sW = Wl;
        sHW = Hl * Wl;
    }
    __syncthreads();

    const float* base = sbase;
    int Wl = sW, HW = sHW;
    float* out = g_X + (size_t)box * FCIN;
    for (int t = threadIdx.x; t < FCIN; t += blockDim.x) {
        int c = t / 49;
        int p = t % 49;
        int gy = p / 7, gx = p % 7;
        out[t] = base[(size_t)c * HW + siy[gy] * Wl + six[gx]];
    }
}

// ---------------- fp32 SGEMM, packed-f32x2 Kahan: C = relu(A @ B + bias) ----
// Bitwise-identical numerics to scalar Kahan with fma(a,b,-cmp):
//   y  = fma2(a, b, m)        (m = -cmp)
//   t  = add2(s, y)
//   d  = fma2(t, -1, s)       (== exact s - t)
//   m' = add2(d, y)           (== -((t-s)-y))
// Two output columns per packed lane pair.
template<bool RELU>
__global__ void __launch_bounds__(256) sgemm_kernel(
    const float* __restrict__ A, const float* __restrict__ B,
    const float* __restrict__ bias, float* __restrict__ Cmat,
    int Mrows, int Kdim, int Ndim)
{
    const int BM = 128, BN = 128, BK = 8;
    __shared__ __align__(16) float As[BK][BM];
    __shared__ __align__(16) float Bs[BK][BN];

    int tid = threadIdx.x;
    int bm = blockIdx.y * BM, bn = blockIdx.x * BN;
    int ty = tid / 16, tx = tid % 16;

    ull s[8][4], m[8][4];
    #pragma unroll
    for (int i = 0; i < 8; i++)
        #pragma unroll
        for (int j = 0; j < 4; j++) { s[i][j] = 0ull; m[i][j] = 0ull; }

    const ull NEG1 = pack2(-1.0f);

    int a_row = tid >> 1;          // 0..127
    int a_k   = (tid & 1) * 4;     // 0 or 4
    int b_k   = tid >> 5;          // 0..7
    int b_n   = (tid & 31) * 4;

    for (int k0 = 0; k0 < Kdim; k0 += BK) {
        float4 av;
        int gr = bm + a_row;
        if (gr < Mrows) av = *(const float4*)(A + (size_t)gr * Kdim + k0 + a_k);
        else            av = make_float4(0.f, 0.f, 0.f, 0.f);
        As[a_k + 0][a_row] = av.x;
        As[a_k + 1][a_row] = av.y;
        As[a_k + 2][a_row] = av.z;
        As[a_k + 3][a_row] = av.w;

        float4 bv = *(const float4*)(B + (size_t)(k0 + b_k) * Ndim + bn + b_n);
        *(float4*)&Bs[b_k][b_n] = bv;
        __syncthreads();

        #pragma unroll
        for (int k = 0; k < BK; k++) {
            ull a2[8], b2[4];
            #pragma unroll
            for (int i = 0; i < 8; i++) a2[i] = pack2(As[k][ty * 8 + i]);
            const ull* brow = reinterpret_cast<const ull*>(&Bs[k][tx * 8]);
            #pragma unroll
            for (int j = 0; j < 4; j++) b2[j] = brow[j];

            #pragma unroll
            for (int i = 0; i < 8; i++) {
                #pragma unroll
                for (int j = 0; j < 4; j++) {
                    ull y = ffma2(a2[i], b2[j], m[i][j]);
                    ull t = fadd2(s[i][j], y);
                    ull d = ffma2(t, NEG1, s[i][j]);   // exact s - t
                    m[i][j] = fadd2(d, y);
                    s[i][j] = t;
                }
            }
        }
        __syncthreads();
    }

    #pragma unroll
    for (int i = 0; i < 8; i++) {
        int r = bm + ty * 8 + i;
        if (r >= Mrows) continue;
        #pragma unroll
        for (int j = 0; j < 4; j++) {
            float2 acc = unpack2(s[i][j]);
            int ccol = bn + tx * 8 + j * 2;
            float v0 = __fadd_rn(acc.x, bias[ccol + 0]);
            float v1 = __fadd_rn(acc.y, bias[ccol + 1]);
            if (RELU) { v0 = fmaxf(v0, 0.0f); v1 = fmaxf(v1, 0.0f); }
            Cmat[(size_t)r * Ndim + ccol + 0] = v0;
            Cmat[(size_t)r * Ndim + ccol + 1] = v1;
        }
    }
}

// ---------------- heads: cls/box projections + softmax + deltas + clip ------
// fp64 accumulation for the 6 small dots (exact ordering-insensitive logits).
__global__ void heads_kernel(const float* __restrict__ Y2,
                             const float* __restrict__ Wc, const float* __restrict__ bc,
                             const float* __restrict__ Wb, const float* __restrict__ bb,
                             const float* __restrict__ props,
                             const int* __restrict__ isz,
                             float* __restrict__ scores, float* __restrict__ pboxes)
{
    int box = blockIdx.x;
    const float* x = Y2 + (size_t)box * FCD;

    double a0 = 0., a1 = 0., a2 = 0., a3 = 0., a4 = 0., a5 = 0.;
    for (int k = threadIdx.x; k < FCD; k += blockDim.x) {
        double xv = (double)x[k];
        a0 += xv * (double)Wc[k * 2 + 0];
        a1 += xv * (double)Wc[k * 2 + 1];
        a2 += xv * (double)Wb[k * 4 + 0];
        a3 += xv * (double)Wb[k * 4 + 1];
        a4 += xv * (double)Wb[k * 4 + 2];
        a5 += xv * (double)Wb[k * 4 + 3];
    }
    __shared__ double red[6][128];
    red[0][threadIdx.x] = a0; red[1][threadIdx.x] = a1; red[2][threadIdx.x] = a2;
    red[3][threadIdx.x] = a3; red[4][threadIdx.x] = a4; red[5][threadIdx.x] = a5;
    __syncthreads();
    for (int s = 64; s > 0; s >>= 1) {
        if (threadIdx.x < s)
            #pragma unroll
            for (int j = 0; j < 6; j++)
                red[j][threadIdx.x] += red[j][threadIdx.x + s];
        __syncthreads();
    }
    if (threadIdx.x == 0) {
        float l0 = (float)(red[0][0] + (double)bc[0]);
        float l1 = (float)(red[1][0] + (double)bc[1]);
        float m = fmaxf(l0, l1);
        float e0 = expf(__fsub_rn(l0, m)), e1 = expf(__fsub_rn(l1, m));
        scores[box] = __fdiv_rn(e1, __fadd_rn(e0, e1));

        float dx = (float)(red[2][0] + (double)bb[0]);
        float dy = (float)(red[3][0] + (double)bb[1]);
        float dw = fminf((float)(red[4][0] + (double)bb[2]), SCALE_CLAMP);
        float dh = fminf((float)(red[5][0] + (double)bb[3]), SCALE_CLAMP);

        const float* pr = props + (size_t)box * 4;
        float w = __fsub_rn(pr[2], pr[0]), h = __fsub_rn(pr[3], pr[1]);
        float cx = __fadd_rn(pr[0], __fmul_rn(0.5f, w));
        float cy = __fadd_rn(pr[1], __fmul_rn(0.5f, h));
        float pcx = __fadd_rn(__fmul_rn(dx, w), cx);
        float pcy = __fadd_rn(__fmul_rn(dy, h), cy);
        float pw = __fmul_rn(expf(dw), w);
        float ph = __fmul_rn(expf(dh), h);

        int img = box / MBOX;
        float Hh = (float)isz[img * 2 + 0];
        float Ww = (float)isz[img * 2 + 1];
        float bx1 = fminf(fmaxf(__fsub_rn(pcx, __fmul_rn(0.5f, pw)), 0.f), Ww);
        float by1 = fminf(fmaxf(__fsub_rn(pcy, __fmul_rn(0.5f, ph)), 0.f), Hh);
        float bx2 = fminf(fmaxf(__fadd_rn(pcx, __fmul_rn(0.5f, pw)), 0.f), Ww);
        float by2 = fminf(fmaxf(__fadd_rn(pcy, __fmul_rn(0.5f, ph)), 0.f), Hh);
        pboxes[box * 4 + 0] = bx1;
        pboxes[box * 4 + 1] = by1;
        pboxes[box * 4 + 2] = bx2;
        pboxes[box * 4 + 3] = by2;
    }
}

// ---------------- per-image stable sort + NMS + topk + write outputs --------
__global__ void __launch_bounds__(512) sortnms_kernel(
    const float* __restrict__ scores, const float* __restrict__ pboxes,
    float* __restrict__ out)
{
    int img = blockIdx.x;
    int tid = threadIdx.x;

    __shared__ float key[SORT_N];
    __shared__ int   idx[SORT_N];
    __shared__ float4 sb[MBOX];
    __shared__ float  sarea[MBOX];
    __shared__ unsigned long long keepw[NWORDS];

    for (int i = tid; i < SORT_N; i += 512) {
        if (i < MBOX) { key[i] = scores[img * MBOX + i]; idx[i] = i; }
        else          { key[i] = -FLT_MAX;               idx[i] = i; }
    }
    __syncthreads();

    // bitonic sort: descending score, tie-break ascending index (stable argsort)
    for (int k = 2; k <= SORT_N; k <<= 1) {
        for (int j = k >> 1; j > 0; j >>= 1) {
            for (int i = tid; i < SORT_N; i += 512) {
                int ixj = i ^ j;
                if (ixj > i) {
                    float ka = key[i], kb = key[ixj];
                    int ia = idx[i], ib = idx[ixj];
                    bool a_before_b = (ka > kb) || (ka == kb && ia < ib);
                    bool up = ((i & k) == 0);
                    bool sw = up ? !a_before_b : a_before_b;
                    if (sw) { key[i] = kb; key[ixj] = ka; idx[i] = ib; idx[ixj] = ia; }
                }
            }
            __syncthreads();
        }
    }

    // gather sorted boxes (already clipped)
    for (int i = tid; i < MBOX; i += 512) {
        const float* p = pboxes + (size_t)(img * MBOX + idx[i]) * 4;
        float4 b = make_float4(p[0], p[1], p[2], p[3]);
        sb[i] = b;
        sarea[i] = (b.z - b.x) * (b.w - b.y);
    }
    __syncthreads();

    // suppression bitmask: sup[i][w] bit jj set iff iou(i, w*64+jj) > T and j > i
    unsigned long long* sup = g_sup + (size_t)img * MBOX * NWORDS;
    for (int t = tid; t < MBOX * NWORDS; t += 512) {
        int i = t / NWORDS, w = t % NWORDS;
        float4 a = sb[i];
        float aa = sarea[i];
        unsigned long long m = 0ull;
        int j0 = w * 64;
        int jend = min(j0 + 64, MBOX);
        for (int j = max(j0, i + 1); j < jend; j++) {
            float4 b = sb[j];
            float lx = fmaxf(a.x, b.x), ly = fmaxf(a.y, b.y);
            float rx = fminf(a.z, b.z), ry = fminf(a.w, b.w);
            float iw = fmaxf(rx - lx, 0.f), ih = fmaxf(ry - ly, 0.f);
            float inter = iw * ih;
            float iou = inter / fmaxf(aa + sarea[j] - inter, 1e-9f);
            if (iou > NMS_THRESH) m |= 1ull << (j - j0);
        }
        sup[t] = m;
    }
    if (tid < NWORDS) {
        unsigned long long m = 0ull;
        for (int jj = 0; jj < 64; jj++) {
            int j = tid * 64 + jj;
            if (j < MBOX && key[j] > SCORE_THRESH) m |= 1ull << jj;
        }
        keepw[tid] = m;
    }
    __syncthreads();

    // sequential NMS scan (warp 0)
    if (tid < 32) {
        volatile unsigned long long* kw = keepw;
        for (int i = 0; i < MBOX; i++) {
            unsigned long long kwi = kw[i >> 6];
            __syncwarp();
            if ((kwi >> (i & 63)) & 1ull) {
                if (tid < NWORDS)
                    kw[tid] = kw[tid] & ~sup[(size_t)i * NWORDS + tid];
            }
            __syncwarp();
        }
        if (tid == 0) {
            int cnt = 0;
            for (int i = 0; i < MBOX; i++) {
                int w = i >> 6, b = i & 63;
                if ((kw[w] >> b) & 1ull) {
                    cnt++;
                    if (cnt > TOPK) kw[w] = kw[w] & ~(1ull << b);
                }
            }
        }
    }
    __syncthreads();

    // outputs: [boxes | scores | keep | order] all as float
    float* oB = out;
    float* oS = out + (size_t)NIMG * MBOX * 4;
    float* oK = oS + (size_t)NIMG * MBOX;
    float* oO = oK + (size_t)NIMG * MBOX;
    for (int i = tid; i < MBOX; i += 512) {
        float4 b = sb[i];
        size_t o = (size_t)(img * MBOX + i);
        oB[o * 4 + 0] = b.x;
        oB[o * 4 + 1] = b.y;
        oB[o * 4 + 2] = b.z;
        oB[o * 4 + 3] = b.w;
        oS[o] = key[i];
        int w = i >> 6, bb2 = i & 63;
        oK[o] = ((keepw[w] >> bb2) & 1ull) ? 1.0f : 0.0f;
        oO[o] = (float)idx[i];
    }
}

// ---------------- launcher ---------------------------------------------------
extern "C" void kernel_launch(void* const* d_in, const int* in_sizes, int n_in,
                              void* d_out, int out_size)
{
    const float* p2    = (const float*)d_in[0];
    const float* p3    = (const float*)d_in[1];
    const float* p4    = (const float*)d_in[2];
    const float* p5    = (const float*)d_in[3];
    const float* props = (const float*)d_in[4];
    const int*   isz   = (const int*)  d_in[5];
    const float* W1    = (const float*)d_in[6];
    const float* b1    = (const float*)d_in[7];
    const float* W2    = (const float*)d_in[8];
    const float* b2    = (const float*)d_in[9];
    const float* Wc    = (const float*)d_in[10];
    const float* bc    = (const float*)d_in[11];
    const float* Wb    = (const float*)d_in[12];
    const float* bb    = (const float*)d_in[13];
    float* out = (float*)d_out;

    void *pX, *pY1, *pY2, *pSc, *pPb;
    cudaGetSymbolAddress(&pX,  g_X);
    cudaGetSymbolAddress(&pY1, g_Y1);
    cudaGetSymbolAddress(&pY2, g_Y2);
    cudaGetSymbolAddress(&pSc, g_scores);
    cudaGetSymbolAddress(&pPb, g_pboxes);
    float* X  = (float*)pX;
    float* Y1 = (float*)pY1;
    float* Y2 = (float*)pY2;
    float* Sc = (float*)pSc;
    float* Pb = (float*)pPb;

    pool_kernel<<<NBOX, 256>>>(p2, p3, p4, p5, props);

    dim3 g1(FCD / 128, (NBOX + 127) / 128);
    sgemm_kernel<true><<<g1, 256>>>(X, W1, b1, Y1, NBOX, FCIN, FCD);
    sgemm_kernel<true><<<g1, 256>>>(Y1, W2, b2, Y2, NBOX, FCD, FCD);

    heads_kernel<<<NBOX, 128>>>(Y2, Wc, bc, Wb, bb, props, isz, Sc, Pb);

    sortnms_kernel<<<NIMG, 512>>>(Sc, Pb, out);
}

// round 4
// speedup vs baseline: 1.6344x; 1.6340x over previous
#include <cuda_runtime.h>
#include <math.h>
#include <float.h>

// Problem constants (fixed shapes from reference setup_inputs)
#define NIMG 2
#define MBOX 1000
#define NBOX (NIMG*MBOX)
#define CCH  256
#define RR   7
#define FCIN (CCH*RR*RR)      // 12544
#define FCD  1024
#define SORT_N 1024
#define NWORDS 16             // ceil(1000/64)
#define SCORE_THRESH 0.05f
#define NMS_THRESH 0.5f
#define TOPK 100
#define SCALE_CLAMP 4.135166556742356f  // log(1000/16)

// ---------------- scratch (device globals; no allocations allowed) ----------
__device__ float g_X [NBOX * FCIN];   // pooled features, row-major (2000 x 12544)
__device__ float g_Y1[NBOX * FCD];
__device__ float g_Y2[NBOX * FCD];
__device__ float g_scores[NBOX];
__device__ float g_pboxes[NBOX * 4];  // clipped predicted boxes
__device__ unsigned long long g_sup[NIMG * MBOX * NWORDS];

// ---------------- pooling (ROIAlign-nearest per reference) ------------------
__global__ void pool_kernel(const float* __restrict__ p2, const float* __restrict__ p3,
                            const float* __restrict__ p4, const float* __restrict__ p5,
                            const float* __restrict__ props)
{
    int box = blockIdx.x;           // 0..1999
    int img = box / MBOX;

    __shared__ int six[RR], siy[RR];
    __shared__ const float* sbase;
    __shared__ int sW, sHW;

    if (threadIdx.x == 0) {
        const float* fmaps[4] = {p2, p3, p4, p5};
        const int   Hs[4] = {200, 100, 50, 25};
        const int   Ws[4] = {304, 152, 76, 38};
        const float sc4[4] = {0.25f, 0.125f, 0.0625f, 0.03125f};

        const float* pr = props + (size_t)box * 4;
        float x1o = pr[0], y1o = pr[1], x2o = pr[2], y2o = pr[3];

        float w = __fsub_rn(x2o, x1o);
        float h = __fsub_rn(y2o, y1o);
        float s = sqrtf(fmaxf(__fmul_rn(w, h), 1e-6f));
        float lv = floorf(__fadd_rn(4.0f, log2f(__fadd_rn(__fdiv_rn(s, 224.0f), 1e-8f))));
        lv = fminf(fmaxf(lv, 2.0f), 5.0f);
        int lvl = (int)lv - 2;      // 0..3

        float sc = sc4[lvl];        // powers of two: multiply is exact
        float x1 = __fmul_rn(x1o, sc), y1 = __fmul_rn(y1o, sc);
        float x2 = __fmul_rn(x2o, sc), y2 = __fmul_rn(y2o, sc);
        float bw = __fdiv_rn(fmaxf(__fsub_rn(x2, x1), 1.0f), 7.0f);
        float bh = __fdiv_rn(fmaxf(__fsub_rn(y2, y1), 1.0f), 7.0f);
        int Wl = Ws[lvl], Hl = Hs[lvl];
        for (int j = 0; j < RR; j++) {
            float cs = (float)j + 0.5f;
            float gx = __fadd_rn(x1, __fmul_rn(cs, bw));
            float gy = __fadd_rn(y1, __fmul_rn(cs, bh));
            int ix = (int)gx;
            int iy = (int)gy;
            six[j] = min(max(ix, 0), Wl - 1);
            siy[j] = min(max(iy, 0), Hl - 1);
        }
        sbase = fmaps[lvl] + (size_t)img * CCH * Hl * Wl;
        sW = Wl;
        sHW = Hl * Wl;
    }
    __syncthreads();

    const float* base = sbase;
    int Wl = sW, HW = sHW;
    float* out = g_X + (size_t)box * FCIN;
    for (int t = threadIdx.x; t < FCIN; t += blockDim.x) {
        int c = t / 49;
        int p = t % 49;
        int gy = p / 7, gx = p % 7;
        out[t] = base[(size_t)c * HW + siy[gy] * Wl + six[gx]];
    }
}

// ---------------- fp32 SGEMM, chunked-compensated: C = relu(A @ B + bias) ---
// Per accumulator: plain FFMA chain over the BK=8 chunk into y (seeded with
// the previous compensation term), then fast2sum fold into master s:
//   t = s + y;  m' = (s - t) + y;  s = t;  (y starts next chunk at m')
// 11 fp ops per 8 MACs (vs 32 for per-MAC Kahan). All explicit-rounding
// intrinsics so the compiler cannot reassociate.
template<bool RELU>
__global__ void __launch_bounds__(256) sgemm_kernel(
    const float* __restrict__ A, const float* __restrict__ B,
    const float* __restrict__ bias, float* __restrict__ Cmat,
    int Mrows, int Kdim, int Ndim)
{
    const int BM = 128, BN = 128, BK = 8;
    __shared__ __align__(16) float As[BK][BM];
    __shared__ __align__(16) float Bs[BK][BN];

    int tid = threadIdx.x;
    int bm = blockIdx.y * BM, bn = blockIdx.x * BN;
    int ty = tid / 16, tx = tid % 16;

    float s[8][8];   // master sums
    float y[8][8];   // chunk partial (starts at compensation term)
    #pragma unroll
    for (int i = 0; i < 8; i++)
        #pragma unroll
        for (int j = 0; j < 8; j++) { s[i][j] = 0.0f; y[i][j] = 0.0f; }

    int a_row = tid >> 1;          // 0..127
    int a_k   = (tid & 1) * 4;     // 0 or 4
    int b_k   = tid >> 5;          // 0..7
    int b_n   = (tid & 31) * 4;

    for (int k0 = 0; k0 < Kdim; k0 += BK) {
        float4 av;
        int gr = bm + a_row;
        if (gr < Mrows) av = *(const float4*)(A + (size_t)gr * Kdim + k0 + a_k);
        else            av = make_float4(0.f, 0.f, 0.f, 0.f);
        As[a_k + 0][a_row] = av.x;
        As[a_k + 1][a_row] = av.y;
        As[a_k + 2][a_row] = av.z;
        As[a_k + 3][a_row] = av.w;

        float4 bv = *(const float4*)(B + (size_t)(k0 + b_k) * Ndim + bn + b_n);
        *(float4*)&Bs[b_k][b_n] = bv;
        __syncthreads();

        // plain FFMA chain over the 8-k chunk (y accumulates products)
        #pragma unroll
        for (int k = 0; k < BK; k++) {
            float ar[8], br[8];
            const float4* ap = (const float4*)&As[k][ty * 8];
            float4 A0 = ap[0], A1 = ap[1];
            ar[0]=A0.x; ar[1]=A0.y; ar[2]=A0.z; ar[3]=A0.w;
            ar[4]=A1.x; ar[5]=A1.y; ar[6]=A1.z; ar[7]=A1.w;
            const float4* bp = (const float4*)&Bs[k][tx * 8];
            float4 B0 = bp[0], B1 = bp[1];
            br[0]=B0.x; br[1]=B0.y; br[2]=B0.z; br[3]=B0.w;
            br[4]=B1.x; br[5]=B1.y; br[6]=B1.z; br[7]=B1.w;

            #pragma unroll
            for (int i = 0; i < 8; i++)
                #pragma unroll
                for (int j = 0; j < 8; j++)
                    y[i][j] = __fmaf_rn(ar[i], br[j], y[i][j]);
        }

        // fast2sum fold: s += y exactly (error captured back into y)
        #pragma unroll
        for (int i = 0; i < 8; i++) {
            #pragma unroll
            for (int j = 0; j < 8; j++) {
                float yo = y[i][j];
                float t  = __fadd_rn(s[i][j], yo);
                y[i][j]  = __fadd_rn(__fsub_rn(s[i][j], t), yo);
                s[i][j]  = t;
            }
        }
        __syncthreads();
    }

    #pragma unroll
    for (int i = 0; i < 8; i++) {
        int r = bm + ty * 8 + i;
        if (r >= Mrows) continue;
        #pragma unroll
        for (int j = 0; j < 8; j++) {
            int ccol = bn + tx * 8 + j;
            // include residual y before bias for a tad more accuracy
            float v = __fadd_rn(__fadd_rn(s[i][j], y[i][j]), bias[ccol]);
            if (RELU) v = fmaxf(v, 0.0f);
            Cmat[(size_t)r * Ndim + ccol] = v;
        }
    }
}

// ---------------- heads: cls/box projections + softmax + deltas + clip ------
// fp64 accumulation for the 6 small dots (exact ordering-insensitive logits).
__global__ void heads_kernel(const float* __restrict__ Y2,
                             const float* __restrict__ Wc, const float* __restrict__ bc,
                             const float* __restrict__ Wb, const float* __restrict__ bb,
                             const float* __restrict__ props,
                             const int* __restrict__ isz,
                             float* __restrict__ scores, float* __restrict__ pboxes)
{
    int box = blockIdx.x;
    const float* x = Y2 + (size_t)box * FCD;

    double a0 = 0., a1 = 0., a2 = 0., a3 = 0., a4 = 0., a5 = 0.;
    for (int k = threadIdx.x; k < FCD; k += blockDim.x) {
        double xv = (double)x[k];
        a0 += xv * (double)Wc[k * 2 + 0];
        a1 += xv * (double)Wc[k * 2 + 1];
        a2 += xv * (double)Wb[k * 4 + 0];
        a3 += xv * (double)Wb[k * 4 + 1];
        a4 += xv * (double)Wb[k * 4 + 2];
        a5 += xv * (double)Wb[k * 4 + 3];
    }
    __shared__ double red[6][128];
    red[0][threadIdx.x] = a0; red[1][threadIdx.x] = a1; red[2][threadIdx.x] = a2;
    red[3][threadIdx.x] = a3; red[4][threadIdx.x] = a4; red[5][threadIdx.x] = a5;
    __syncthreads();
    for (int s = 64; s > 0; s >>= 1) {
        if (threadIdx.x < s)
            #pragma unroll
            for (int j = 0; j < 6; j++)
                red[j][threadIdx.x] += red[j][threadIdx.x + s];
        __syncthreads();
    }
    if (threadIdx.x == 0) {
        float l0 = (float)(red[0][0] + (double)bc[0]);
        float l1 = (float)(red[1][0] + (double)bc[1]);
        float m = fmaxf(l0, l1);
        float e0 = expf(__fsub_rn(l0, m)), e1 = expf(__fsub_rn(l1, m));
        scores[box] = __fdiv_rn(e1, __fadd_rn(e0, e1));

        float dx = (float)(red[2][0] + (double)bb[0]);
        float dy = (float)(red[3][0] + (double)bb[1]);
        float dw = fminf((float)(red[4][0] + (double)bb[2]), SCALE_CLAMP);
        float dh = fminf((float)(red[5][0] + (double)bb[3]), SCALE_CLAMP);

        const float* pr = props + (size_t)box * 4;
        float w = __fsub_rn(pr[2], pr[0]), h = __fsub_rn(pr[3], pr[1]);
        float cx = __fadd_rn(pr[0], __fmul_rn(0.5f, w));
        float cy = __fadd_rn(pr[1], __fmul_rn(0.5f, h));
        float pcx = __fadd_rn(__fmul_rn(dx, w), cx);
        float pcy = __fadd_rn(__fmul_rn(dy, h), cy);
        float pw = __fmul_rn(expf(dw), w);
        float ph = __fmul_rn(expf(dh), h);

        int img = box / MBOX;
        float Hh = (float)isz[img * 2 + 0];
        float Ww = (float)isz[img * 2 + 1];
        float bx1 = fminf(fmaxf(__fsub_rn(pcx, __fmul_rn(0.5f, pw)), 0.f), Ww);
        float by1 = fminf(fmaxf(__fsub_rn(pcy, __fmul_rn(0.5f, ph)), 0.f), Hh);
        float bx2 = fminf(fmaxf(__fadd_rn(pcx, __fmul_rn(0.5f, pw)), 0.f), Ww);
        float by2 = fminf(fmaxf(__fadd_rn(pcy, __fmul_rn(0.5f, ph)), 0.f), Hh);
        pboxes[box * 4 + 0] = bx1;
        pboxes[box * 4 + 1] = by1;
        pboxes[box * 4 + 2] = bx2;
        pboxes[box * 4 + 3] = by2;
    }
}

// ---------------- per-image stable sort + NMS + topk + write outputs --------
__global__ void __launch_bounds__(512) sortnms_kernel(
    const float* __restrict__ scores, const float* __restrict__ pboxes,
    float* __restrict__ out)
{
    int img = blockIdx.x;
    int tid = threadIdx.x;

    __shared__ float key[SORT_N];
    __shared__ int   idx[SORT_N];
    __shared__ float4 sb[MBOX];
    __shared__ float  sarea[MBOX];
    __shared__ unsigned long long keepw[NWORDS];

    for (int i = tid; i < SORT_N; i += 512) {
        if (i < MBOX) { key[i] = scores[img * MBOX + i]; idx[i] = i; }
        else          { key[i] = -FLT_MAX;               idx[i] = i; }
    }
    __syncthreads();

    // bitonic sort: descending score, tie-break ascending index (stable argsort)
    for (int k = 2; k <= SORT_N; k <<= 1) {
        for (int j = k >> 1; j > 0; j >>= 1) {
            for (int i = tid; i < SORT_N; i += 512) {
                int ixj = i ^ j;
                if (ixj > i) {
                    float ka = key[i], kb = key[ixj];
                    int ia = idx[i], ib = idx[ixj];
                    bool a_before_b = (ka > kb) || (ka == kb && ia < ib);
                    bool up = ((i & k) == 0);
                    bool sw = up ? !a_before_b : a_before_b;
                    if (sw) { key[i] = kb; key[ixj] = ka; idx[i] = ib; idx[ixj] = ia; }
                }
            }
            __syncthreads();
        }
    }

    // gather sorted boxes (already clipped)
    for (int i = tid; i < MBOX; i += 512) {
        const float* p = pboxes + (size_t)(img * MBOX + idx[i]) * 4;
        float4 b = make_float4(p[0], p[1], p[2], p[3]);
        sb[i] = b;
        sarea[i] = (b.z - b.x) * (b.w - b.y);
    }
    __syncthreads();

    // suppression bitmask: sup[i][w] bit jj set iff iou(i, w*64+jj) > T and j > i
    unsigned long long* sup = g_sup + (size_t)img * MBOX * NWORDS;
    for (int t = tid; t < MBOX * NWORDS; t += 512) {
        int i = t / NWORDS, w = t % NWORDS;
        float4 a = sb[i];
        float aa = sarea[i];
        unsigned long long m = 0ull;
        int j0 = w * 64;
        int jend = min(j0 + 64, MBOX);
        for (int j = max(j0, i + 1); j < jend; j++) {
            float4 b = sb[j];
            float lx = fmaxf(a.x, b.x), ly = fmaxf(a.y, b.y);
            float rx = fminf(a.z, b.z), ry = fminf(a.w, b.w);
            float iw = fmaxf(rx - lx, 0.f), ih = fmaxf(ry - ly, 0.f);
            float inter = iw * ih;
            float iou = inter / fmaxf(aa + sarea[j] - inter, 1e-9f);
            if (iou > NMS_THRESH) m |= 1ull << (j - j0);
        }
        sup[t] = m;
    }
    if (tid < NWORDS) {
        unsigned long long m = 0ull;
        for (int jj = 0; jj < 64; jj++) {
            int j = tid * 64 + jj;
            if (j < MBOX && key[j] > SCORE_THRESH) m |= 1ull << jj;
        }
        keepw[tid] = m;
    }
    __syncthreads();

    // sequential NMS scan (warp 0)
    if (tid < 32) {
        volatile unsigned long long* kw = keepw;
        for (int i = 0; i < MBOX; i++) {
            unsigned long long kwi = kw[i >> 6];
            __syncwarp();
            if ((kwi >> (i & 63)) & 1ull) {
                if (tid < NWORDS)
                    kw[tid] = kw[tid] & ~sup[(size_t)i * NWORDS + tid];
            }
            __syncwarp();
        }
        if (tid == 0) {
            int cnt = 0;
            for (int i = 0; i < MBOX; i++) {
                int w = i >> 6, b = i & 63;
                if ((kw[w] >> b) & 1ull) {
                    cnt++;
                    if (cnt > TOPK) kw[w] = kw[w] & ~(1ull << b);
                }
            }
        }
    }
    __syncthreads();

    // outputs: [boxes | scores | keep | order] all as float
    float* oB = out;
    float* oS = out + (size_t)NIMG * MBOX * 4;
    float* oK = oS + (size_t)NIMG * MBOX;
    float* oO = oK + (size_t)NIMG * MBOX;
    for (int i = tid; i < MBOX; i += 512) {
        float4 b = sb[i];
        size_t o = (size_t)(img * MBOX + i);
        oB[o * 4 + 0] = b.x;
        oB[o * 4 + 1] = b.y;
        oB[o * 4 + 2] = b.z;
        oB[o * 4 + 3] = b.w;
        oS[o] = key[i];
        int w = i >> 6, bb2 = i & 63;
        oK[o] = ((keepw[w] >> bb2) & 1ull) ? 1.0f : 0.0f;
        oO[o] = (float)idx[i];
    }
}

// ---------------- launcher ---------------------------------------------------
extern "C" void kernel_launch(void* const* d_in, const int* in_sizes, int n_in,
                              void* d_out, int out_size)
{
    const float* p2    = (const float*)d_in[0];
    const float* p3    = (const float*)d_in[1];
    const float* p4    = (const float*)d_in[2];
    const float* p5    = (const float*)d_in[3];
    const float* props = (const float*)d_in[4];
    const int*   isz   = (const int*)  d_in[5];
    const float* W1    = (const float*)d_in[6];
    const float* b1    = (const float*)d_in[7];
    const float* W2    = (const float*)d_in[8];
    const float* b2    = (const float*)d_in[9];
    const float* Wc    = (const float*)d_in[10];
    const float* bc    = (const float*)d_in[11];
    const float* Wb    = (const float*)d_in[12];
    const float* bb    = (const float*)d_in[13];
    float* out = (float*)d_out;

    void *pX, *pY1, *pY2, *pSc, *pPb;
    cudaGetSymbolAddress(&pX,  g_X);
    cudaGetSymbolAddress(&pY1, g_Y1);
    cudaGetSymbolAddress(&pY2, g_Y2);
    cudaGetSymbolAddress(&pSc, g_scores);
    cudaGetSymbolAddress(&pPb, g_pboxes);
    float* X  = (float*)pX;
    float* Y1 = (float*)pY1;
    float* Y2 = (float*)pY2;
    float* Sc = (float*)pSc;
    float* Pb = (float*)pPb;

    pool_kernel<<<NBOX, 256>>>(p2, p3, p4, p5, props);

    dim3 g1(FCD / 128, (NBOX + 127) / 128);
    sgemm_kernel<true><<<g1, 256>>>(X, W1, b1, Y1, NBOX, FCIN, FCD);
    sgemm_kernel<true><<<g1, 256>>>(Y1, W2, b2, Y2, NBOX, FCD, FCD);

    heads_kernel<<<NBOX, 128>>>(Y2, Wc, bc, Wb, bb, props, isz, Sc, Pb);

    sortnms_kernel<<<NIMG, 512>>>(Sc, Pb, out);
}

// round 5
// speedup vs baseline: 2.0704x; 1.2668x over previous
#include <cuda_runtime.h>
#include <math.h>
#include <float.h>

// Problem constants (fixed shapes from reference setup_inputs)
#define NIMG 2
#define MBOX 1000
#define NBOX (NIMG*MBOX)
#define CCH  256
#define RR   7
#define FCIN (CCH*RR*RR)      // 12544
#define FCD  1024
#define SORT_N 1024
#define NWORDS 16             // ceil(1000/64)
#define SCORE_THRESH 0.05f
#define NMS_THRESH 0.5f
#define TOPK 100
#define SCALE_CLAMP 4.135166556742356f  // log(1000/16)

// ---------------- scratch (device globals; no allocations allowed) ----------
__device__ float g_X [NBOX * FCIN];   // pooled features, row-major (2000 x 12544)
__device__ float g_Y1[NBOX * FCD];
__device__ float g_Y2[NBOX * FCD];
__device__ float g_scores[NBOX];
__device__ float g_pboxes[NBOX * 4];  // clipped predicted boxes
__device__ unsigned long long g_sup[NIMG * MBOX * NWORDS];

// ---------------- pooling (ROIAlign-nearest per reference) ------------------
__global__ void pool_kernel(const float* __restrict__ p2, const float* __restrict__ p3,
                            const float* __restrict__ p4, const float* __restrict__ p5,
                            const float* __restrict__ props)
{
    int box = blockIdx.x;           // 0..1999
    int img = box / MBOX;

    __shared__ int six[RR], siy[RR];
    __shared__ const float* sbase;
    __shared__ int sW, sHW;

    if (threadIdx.x == 0) {
        const float* fmaps[4] = {p2, p3, p4, p5};
        const int   Hs[4] = {200, 100, 50, 25};
        const int   Ws[4] = {304, 152, 76, 38};
        const float sc4[4] = {0.25f, 0.125f, 0.0625f, 0.03125f};

        const float* pr = props + (size_t)box * 4;
        float x1o = pr[0], y1o = pr[1], x2o = pr[2], y2o = pr[3];

        float w = __fsub_rn(x2o, x1o);
        float h = __fsub_rn(y2o, y1o);
        float s = sqrtf(fmaxf(__fmul_rn(w, h), 1e-6f));
        float lv = floorf(__fadd_rn(4.0f, log2f(__fadd_rn(__fdiv_rn(s, 224.0f), 1e-8f))));
        lv = fminf(fmaxf(lv, 2.0f), 5.0f);
        int lvl = (int)lv - 2;      // 0..3

        float sc = sc4[lvl];        // powers of two: multiply is exact
        float x1 = __fmul_rn(x1o, sc), y1 = __fmul_rn(y1o, sc);
        float x2 = __fmul_rn(x2o, sc), y2 = __fmul_rn(y2o, sc);
        float bw = __fdiv_rn(fmaxf(__fsub_rn(x2, x1), 1.0f), 7.0f);
        float bh = __fdiv_rn(fmaxf(__fsub_rn(y2, y1), 1.0f), 7.0f);
        int Wl = Ws[lvl], Hl = Hs[lvl];
        for (int j = 0; j < RR; j++) {
            float cs = (float)j + 0.5f;
            float gx = __fadd_rn(x1, __fmul_rn(cs, bw));
            float gy = __fadd_rn(y1, __fmul_rn(cs, bh));
            int ix = (int)gx;
            int iy = (int)gy;
            six[j] = min(max(ix, 0), Wl - 1);
            siy[j] = min(max(iy, 0), Hl - 1);
        }
        sbase = fmaps[lvl] + (size_t)img * CCH * Hl * Wl;
        sW = Wl;
        sHW = Hl * Wl;
    }
    __syncthreads();

    const float* base = sbase;
    int Wl = sW, HW = sHW;
    float* out = g_X + (size_t)box * FCIN;
    for (int t = threadIdx.x; t < FCIN; t += blockDim.x) {
        int c = t / 49;
        int p = t % 49;
        int gy = p / 7, gx = p % 7;
        out[t] = base[(size_t)c * HW + siy[gy] * Wl + six[gx]];
    }
}

// ---------------- fp32 SGEMM, chunked-compensated, double-buffered ----------
// BK=16 chunk: plain FFMA chain into y (seeded with prev compensation), then
// one fast2sum fold into master s per chunk: 1 + 3/16 fp ops per MAC.
// Double-buffered smem + register prefetch hides global-load latency; one
// barrier per 16 k.
template<bool RELU>
__global__ void __launch_bounds__(256) sgemm_kernel(
    const float* __restrict__ A, const float* __restrict__ B,
    const float* __restrict__ bias, float* __restrict__ Cmat,
    int Mrows, int Kdim, int Ndim)
{
    const int BM = 128, BN = 128, BK = 16;
    __shared__ __align__(16) float As[2][BK][BM];
    __shared__ __align__(16) float Bs[2][BK][BN];

    int tid = threadIdx.x;
    int bm = blockIdx.y * BM, bn = blockIdx.x * BN;
    int ty = tid / 16, tx = tid % 16;

    float s[8][8];   // master sums
    float y[8][8];   // chunk partial (starts at compensation term)
    #pragma unroll
    for (int i = 0; i < 8; i++)
        #pragma unroll
        for (int j = 0; j < 8; j++) { s[i][j] = 0.0f; y[i][j] = 0.0f; }

    // load mapping
    int a_row = tid >> 1;          // 0..127
    int a_k   = (tid & 1) * 8;     // 0 or 8  (two float4 at +0, +4)
    int b_k   = tid >> 4;          // 0..15
    int b_n   = (tid & 15) * 8;    // two float4 at +0, +4

    int gr = bm + a_row;
    bool a_ok = (gr < Mrows);
    const float* Aptr = A + (size_t)(a_ok ? gr : 0) * Kdim + a_k;
    const float* Bptr = B + (size_t)b_k * Ndim + bn + b_n;

    float4 pa0, pa1, pb0, pb1;

    // prologue: fetch tile 0
    if (a_ok) { pa0 = *(const float4*)(Aptr + 0); pa1 = *(const float4*)(Aptr + 4); }
    else      { pa0 = make_float4(0,0,0,0);       pa1 = make_float4(0,0,0,0); }
    pb0 = *(const float4*)(Bptr + 0);
    pb1 = *(const float4*)(Bptr + 4);

    int buf = 0;
    // store tile 0
    As[0][a_k + 0][a_row] = pa0.x; As[0][a_k + 1][a_row] = pa0.y;
    As[0][a_k + 2][a_row] = pa0.z; As[0][a_k + 3][a_row] = pa0.w;
    As[0][a_k + 4][a_row] = pa1.x; As[0][a_k + 5][a_row] = pa1.y;
    As[0][a_k + 6][a_row] = pa1.z; As[0][a_k + 7][a_row] = pa1.w;
    *(float4*)&Bs[0][b_k][b_n + 0] = pb0;
    *(float4*)&Bs[0][b_k][b_n + 4] = pb1;
    __syncthreads();

    for (int k0 = BK; k0 <= Kdim; k0 += BK) {
        // prefetch next tile into registers (overlaps with compute below)
        if (k0 < Kdim) {
            if (a_ok) { pa0 = *(const float4*)(Aptr + k0 + 0); pa1 = *(const float4*)(Aptr + k0 + 4); }
            pb0 = *(const float4*)(Bptr + (size_t)k0 * Ndim + 0);
            pb1 = *(const float4*)(Bptr + (size_t)k0 * Ndim + 4);
        }

        // compute current chunk: plain FFMA chain into y
        #pragma unroll
        for (int k = 0; k < BK; k++) {
            float ar[8], br[8];
            const float4* ap = (const float4*)&As[buf][k][ty * 8];
            float4 A0 = ap[0], A1 = ap[1];
            ar[0]=A0.x; ar[1]=A0.y; ar[2]=A0.z; ar[3]=A0.w;
            ar[4]=A1.x; ar[5]=A1.y; ar[6]=A1.z; ar[7]=A1.w;
            const float4* bp = (const float4*)&Bs[buf][k][tx * 8];
            float4 B0 = bp[0], B1 = bp[1];
            br[0]=B0.x; br[1]=B0.y; br[2]=B0.z; br[3]=B0.w;
            br[4]=B1.x; br[5]=B1.y; br[6]=B1.z; br[7]=B1.w;

            #pragma unroll
            for (int i = 0; i < 8; i++)
                #pragma unroll
                for (int j = 0; j < 8; j++)
                    y[i][j] = __fmaf_rn(ar[i], br[j], y[i][j]);
        }

        // fast2sum fold: s += y exactly (error captured back into y)
        #pragma unroll
        for (int i = 0; i < 8; i++) {
            #pragma unroll
            for (int j = 0; j < 8; j++) {
                float yo = y[i][j];
                float t  = __fadd_rn(s[i][j], yo);
                y[i][j]  = __fadd_rn(__fsub_rn(s[i][j], t), yo);
                s[i][j]  = t;
            }
        }

        // store prefetched tile into the other buffer
        if (k0 < Kdim) {
            int nb = buf ^ 1;
            As[nb][a_k + 0][a_row] = pa0.x; As[nb][a_k + 1][a_row] = pa0.y;
            As[nb][a_k + 2][a_row] = pa0.z; As[nb][a_k + 3][a_row] = pa0.w;
            As[nb][a_k + 4][a_row] = pa1.x; As[nb][a_k + 5][a_row] = pa1.y;
            As[nb][a_k + 6][a_row] = pa1.z; As[nb][a_k + 7][a_row] = pa1.w;
            *(float4*)&Bs[nb][b_k][b_n + 0] = pb0;
            *(float4*)&Bs[nb][b_k][b_n + 4] = pb1;
            __syncthreads();
            buf = nb;
        }
    }

    #pragma unroll
    for (int i = 0; i < 8; i++) {
        int r = bm + ty * 8 + i;
        if (r >= Mrows) continue;
        #pragma unroll
        for (int j = 0; j < 8; j++) {
            int ccol = bn + tx * 8 + j;
            // include residual y before bias for a tad more accuracy
            float v = __fadd_rn(__fadd_rn(s[i][j], y[i][j]), bias[ccol]);
            if (RELU) v = fmaxf(v, 0.0f);
            Cmat[(size_t)r * Ndim + ccol] = v;
        }
    }
}

// ---------------- heads: cls/box projections + softmax + deltas + clip ------
// fp64 accumulation for the 6 small dots (exact ordering-insensitive logits).
__global__ void heads_kernel(const float* __restrict__ Y2,
                             const float* __restrict__ Wc, const float* __restrict__ bc,
                             const float* __restrict__ Wb, const float* __restrict__ bb,
                             const float* __restrict__ props,
                             const int* __restrict__ isz,
                             float* __restrict__ scores, float* __restrict__ pboxes)
{
    int box = blockIdx.x;
    const float* x = Y2 + (size_t)box * FCD;

    double a0 = 0., a1 = 0., a2 = 0., a3 = 0., a4 = 0., a5 = 0.;
    for (int k = threadIdx.x; k < FCD; k += blockDim.x) {
        double xv = (double)x[k];
        a0 += xv * (double)Wc[k * 2 + 0];
        a1 += xv * (double)Wc[k * 2 + 1];
        a2 += xv * (double)Wb[k * 4 + 0];
        a3 += xv * (double)Wb[k * 4 + 1];
        a4 += xv * (double)Wb[k * 4 + 2];
        a5 += xv * (double)Wb[k * 4 + 3];
    }
    __shared__ double red[6][128];
    red[0][threadIdx.x] = a0; red[1][threadIdx.x] = a1; red[2][threadIdx.x] = a2;
    red[3][threadIdx.x] = a3; red[4][threadIdx.x] = a4; red[5][threadIdx.x] = a5;
    __syncthreads();
    for (int s = 64; s > 0; s >>= 1) {
        if (threadIdx.x < s)
            #pragma unroll
            for (int j = 0; j < 6; j++)
                red[j][threadIdx.x] += red[j][threadIdx.x + s];
        __syncthreads();
    }
    if (threadIdx.x == 0) {
        float l0 = (float)(red[0][0] + (double)bc[0]);
        float l1 = (float)(red[1][0] + (double)bc[1]);
        float m = fmaxf(l0, l1);
        float e0 = expf(__fsub_rn(l0, m)), e1 = expf(__fsub_rn(l1, m));
        scores[box] = __fdiv_rn(e1, __fadd_rn(e0, e1));

        float dx = (float)(red[2][0] + (double)bb[0]);
        float dy = (float)(red[3][0] + (double)bb[1]);
        float dw = fminf((float)(red[4][0] + (double)bb[2]), SCALE_CLAMP);
        float dh = fminf((float)(red[5][0] + (double)bb[3]), SCALE_CLAMP);

        const float* pr = props + (size_t)box * 4;
        float w = __fsub_rn(pr[2], pr[0]), h = __fsub_rn(pr[3], pr[1]);
        float cx = __fadd_rn(pr[0], __fmul_rn(0.5f, w));
        float cy = __fadd_rn(pr[1], __fmul_rn(0.5f, h));
        float pcx = __fadd_rn(__fmul_rn(dx, w), cx);
        float pcy = __fadd_rn(__fmul_rn(dy, h), cy);
        float pw = __fmul_rn(expf(dw), w);
        float ph = __fmul_rn(expf(dh), h);

        int img = box / MBOX;
        float Hh = (float)isz[img * 2 + 0];
        float Ww = (float)isz[img * 2 + 1];
        float bx1 = fminf(fmaxf(__fsub_rn(pcx, __fmul_rn(0.5f, pw)), 0.f), Ww);
        float by1 = fminf(fmaxf(__fsub_rn(pcy, __fmul_rn(0.5f, ph)), 0.f), Hh);
        float bx2 = fminf(fmaxf(__fadd_rn(pcx, __fmul_rn(0.5f, pw)), 0.f), Ww);
        float by2 = fminf(fmaxf(__fadd_rn(pcy, __fmul_rn(0.5f, ph)), 0.f), Hh);
        pboxes[box * 4 + 0] = bx1;
        pboxes[box * 4 + 1] = by1;
        pboxes[box * 4 + 2] = bx2;
        pboxes[box * 4 + 3] = by2;
    }
}

// ---------------- per-image stable sort + NMS + topk + write outputs --------
__global__ void __launch_bounds__(512) sortnms_kernel(
    const float* __restrict__ scores, const float* __restrict__ pboxes,
    float* __restrict__ out)
{
    int img = blockIdx.x;
    int tid = threadIdx.x;

    __shared__ float key[SORT_N];
    __shared__ int   idx[SORT_N];
    __shared__ float4 sb[MBOX];
    __shared__ float  sarea[MBOX];
    __shared__ unsigned long long keepw[NWORDS];

    for (int i = tid; i < SORT_N; i += 512) {
        if (i < MBOX) { key[i] = scores[img * MBOX + i]; idx[i] = i; }
        else          { key[i] = -FLT_MAX;               idx[i] = i; }
    }
    __syncthreads();

    // bitonic sort: descending score, tie-break ascending index (stable argsort)
    for (int k = 2; k <= SORT_N; k <<= 1) {
        for (int j = k >> 1; j > 0; j >>= 1) {
            for (int i = tid; i < SORT_N; i += 512) {
                int ixj = i ^ j;
                if (ixj > i) {
                    float ka = key[i], kb = key[ixj];
                    int ia = idx[i], ib = idx[ixj];
                    bool a_before_b = (ka > kb) || (ka == kb && ia < ib);
                    bool up = ((i & k) == 0);
                    bool sw = up ? !a_before_b : a_before_b;
                    if (sw) { key[i] = kb; key[ixj] = ka; idx[i] = ib; idx[ixj] = ia; }
                }
            }
            __syncthreads();
        }
    }

    // gather sorted boxes (already clipped)
    for (int i = tid; i < MBOX; i += 512) {
        const float* p = pboxes + (size_t)(img * MBOX + idx[i]) * 4;
        float4 b = make_float4(p[0], p[1], p[2], p[3]);
        sb[i] = b;
        sarea[i] = (b.z - b.x) * (b.w - b.y);
    }
    __syncthreads();

    // suppression bitmask: sup[i][w] bit jj set iff iou(i, w*64+jj) > T and j > i
    unsigned long long* sup = g_sup + (size_t)img * MBOX * NWORDS;
    for (int t = tid; t < MBOX * NWORDS; t += 512) {
        int i = t / NWORDS, w = t % NWORDS;
        float4 a = sb[i];
        float aa = sarea[i];
        unsigned long long m = 0ull;
        int j0 = w * 64;
        int jend = min(j0 + 64, MBOX);
        for (int j = max(j0, i + 1); j < jend; j++) {
            float4 b = sb[j];
            float lx = fmaxf(a.x, b.x), ly = fmaxf(a.y, b.y);
            float rx = fminf(a.z, b.z), ry = fminf(a.w, b.w);
            float iw = fmaxf(rx - lx, 0.f), ih = fmaxf(ry - ly, 0.f);
            float inter = iw * ih;
            float iou = inter / fmaxf(aa + sarea[j] - inter, 1e-9f);
            if (iou > NMS_THRESH) m |= 1ull << (j - j0);
        }
        sup[t] = m;
    }
    if (tid < NWORDS) {
        unsigned long long m = 0ull;
        for (int jj = 0; jj < 64; jj++) {
            int j = tid * 64 + jj;
            if (j < MBOX && key[j] > SCORE_THRESH) m |= 1ull << jj;
        }
        keepw[tid] = m;
    }
    __syncthreads();

    // sequential NMS scan (warp 0)
    if (tid < 32) {
        volatile unsigned long long* kw = keepw;
        for (int i = 0; i < MBOX; i++) {
            unsigned long long kwi = kw[i >> 6];
            __syncwarp();
            if ((kwi >> (i & 63)) & 1ull) {
                if (tid < NWORDS)
                    kw[tid] = kw[tid] & ~sup[(size_t)i * NWORDS + tid];
            }
            __syncwarp();
        }
        if (tid == 0) {
            int cnt = 0;
            for (int i = 0; i < MBOX; i++) {
                int w = i >> 6, b = i & 63;
                if ((kw[w] >> b) & 1ull) {
                    cnt++;
                    if (cnt > TOPK) kw[w] = kw[w] & ~(1ull << b);
                }
            }
        }
    }
    __syncthreads();

    // outputs: [boxes | scores | keep | order] all as float
    float* oB = out;
    float* oS = out + (size_t)NIMG * MBOX * 4;
    float* oK = oS + (size_t)NIMG * MBOX;
    float* oO = oK + (size_t)NIMG * MBOX;
    for (int i = tid; i < MBOX; i += 512) {
        float4 b = sb[i];
        size_t o = (size_t)(img * MBOX + i);
        oB[o * 4 + 0] = b.x;
        oB[o * 4 + 1] = b.y;
        oB[o * 4 + 2] = b.z;
        oB[o * 4 + 3] = b.w;
        oS[o] = key[i];
        int w = i >> 6, bb2 = i & 63;
        oK[o] = ((keepw[w] >> bb2) & 1ull) ? 1.0f : 0.0f;
        oO[o] = (float)idx[i];
    }
}

// ---------------- launcher ---------------------------------------------------
extern "C" void kernel_launch(void* const* d_in, const int* in_sizes, int n_in,
                              void* d_out, int out_size)
{
    const float* p2    = (const float*)d_in[0];
    const float* p3    = (const float*)d_in[1];
    const float* p4    = (const float*)d_in[2];
    const float* p5    = (const float*)d_in[3];
    const float* props = (const float*)d_in[4];
    const int*   isz   = (const int*)  d_in[5];
    const float* W1    = (const float*)d_in[6];
    const float* b1    = (const float*)d_in[7];
    const float* W2    = (const float*)d_in[8];
    const float* b2    = (const float*)d_in[9];
    const float* Wc    = (const float*)d_in[10];
    const float* bc    = (const float*)d_in[11];
    const float* Wb    = (const float*)d_in[12];
    const float* bb    = (const float*)d_in[13];
    float* out = (float*)d_out;

    void *pX, *pY1, *pY2, *pSc, *pPb;
    cudaGetSymbolAddress(&pX,  g_X);
    cudaGetSymbolAddress(&pY1, g_Y1);
    cudaGetSymbolAddress(&pY2, g_Y2);
    cudaGetSymbolAddress(&pSc, g_scores);
    cudaGetSymbolAddress(&pPb, g_pboxes);
    float* X  = (float*)pX;
    float* Y1 = (float*)pY1;
    float* Y2 = (float*)pY2;
    float* Sc = (float*)pSc;
    float* Pb = (float*)pPb;

    pool_kernel<<<NBOX, 256>>>(p2, p3, p4, p5, props);

    dim3 g1(FCD / 128, (NBOX + 127) / 128);
    sgemm_kernel<true><<<g1, 256>>>(X, W1, b1, Y1, NBOX, FCIN, FCD);
    sgemm_kernel<true><<<g1, 256>>>(Y1, W2, b2, Y2, NBOX, FCD, FCD);

    heads_kernel<<<NBOX, 128>>>(Y2, Wc, bc, Wb, bb, props, isz, Sc, Pb);

    sortnms_kernel<<<NIMG, 512>>>(Sc, Pb, out);
}

// round 7
// speedup vs baseline: 2.2770x; 1.0998x over previous
#include <cuda_runtime.h>
#include <math.h>
#include <float.h>

// Problem constants (fixed shapes from reference setup_inputs)
#define NIMG 2
#define MBOX 1000
#define NBOX (NIMG*MBOX)
#define CCH  256
#define RR   7
#define FCIN (CCH*RR*RR)      // 12544
#define FCD  1024
#define SORT_N 1024
#define NWORDS 16             // ceil(1000/64)
#define SCORE_THRESH 0.05f
#define NMS_THRESH 0.5f
#define TOPK 100
#define SCALE_CLAMP 4.135166556742356f  // log(1000/16)

// ---------------- scratch (device globals; no allocations allowed) ----------
__device__ float g_X [NBOX * FCIN];   // pooled features, row-major (2000 x 12544)
__device__ float g_Y1[NBOX * FCD];
__device__ float g_Y2[NBOX * FCD];
__device__ float g_scores[NBOX];
__device__ float g_pboxes[NBOX * 4];  // clipped predicted boxes
__device__ unsigned long long g_sup[NIMG * MBOX * NWORDS];

// ---------------- pooling (ROIAlign-nearest per reference) ------------------
__global__ void pool_kernel(const float* __restrict__ p2, const float* __restrict__ p3,
                            const float* __restrict__ p4, const float* __restrict__ p5,
                            const float* __restrict__ props)
{
    int box = blockIdx.x;           // 0..1999
    int img = box / MBOX;

    __shared__ int six[RR], siy[RR];
    __shared__ const float* sbase;
    __shared__ int sW, sHW;

    if (threadIdx.x == 0) {
        const float* fmaps[4] = {p2, p3, p4, p5};
        const int   Hs[4] = {200, 100, 50, 25};
        const int   Ws[4] = {304, 152, 76, 38};
        const float sc4[4] = {0.25f, 0.125f, 0.0625f, 0.03125f};

        const float* pr = props + (size_t)box * 4;
        float x1o = pr[0], y1o = pr[1], x2o = pr[2], y2o = pr[3];

        float w = __fsub_rn(x2o, x1o);
        float h = __fsub_rn(y2o, y1o);
        float s = sqrtf(fmaxf(__fmul_rn(w, h), 1e-6f));
        float lv = floorf(__fadd_rn(4.0f, log2f(__fadd_rn(__fdiv_rn(s, 224.0f), 1e-8f))));
        lv = fminf(fmaxf(lv, 2.0f), 5.0f);
        int lvl = (int)lv - 2;      // 0..3

        float sc = sc4[lvl];        // powers of two: multiply is exact
        float x1 = __fmul_rn(x1o, sc), y1 = __fmul_rn(y1o, sc);
        float x2 = __fmul_rn(x2o, sc), y2 = __fmul_rn(y2o, sc);
        float bw = __fdiv_rn(fmaxf(__fsub_rn(x2, x1), 1.0f), 7.0f);
        float bh = __fdiv_rn(fmaxf(__fsub_rn(y2, y1), 1.0f), 7.0f);
        int Wl = Ws[lvl], Hl = Hs[lvl];
        for (int j = 0; j < RR; j++) {
            float cs = (float)j + 0.5f;
            float gx = __fadd_rn(x1, __fmul_rn(cs, bw));
            float gy = __fadd_rn(y1, __fmul_rn(cs, bh));
            int ix = (int)gx;
            int iy = (int)gy;
            six[j] = min(max(ix, 0), Wl - 1);
            siy[j] = min(max(iy, 0), Hl - 1);
        }
        sbase = fmaps[lvl] + (size_t)img * CCH * Hl * Wl;
        sW = Wl;
        sHW = Hl * Wl;
    }
    __syncthreads();

    const float* base = sbase;
    int Wl = sW, HW = sHW;
    float* out = g_X + (size_t)box * FCIN;
    for (int t = threadIdx.x; t < FCIN; t += blockDim.x) {
        int c = t / 49;
        int p = t % 49;
        int gy = p / 7, gx = p % 7;
        out[t] = base[(size_t)c * HW + siy[gy] * Wl + six[gx]];
    }
}

// ---------------- fp32 SGEMM, chunked-compensated, double-buffered ----------
// BK=16 tiles, double-buffered with register prefetch. Plain FFMA chain into
// y; fold y into master s with one fast2sum every FOLD_EVERY=4 tiles (64 k):
// 1 + 3/64 fp ops per MAC. Kdim must be a multiple of BK*FOLD_EVERY.
template<bool RELU>
__global__ void __launch_bounds__(256) sgemm_kernel(
    const float* __restrict__ A, const float* __restrict__ B,
    const float* __restrict__ bias, float* __restrict__ Cmat,
    int Mrows, int Kdim, int Ndim)
{
    const int BM = 128, BN = 128, BK = 16;
    const int FOLD_EVERY = 4;     // fold every 4 tiles = 64 k
    __shared__ __align__(16) float As[2][BK][BM];
    __shared__ __align__(16) float Bs[2][BK][BN];

    int tid = threadIdx.x;
    int bm = blockIdx.y * BM, bn = blockIdx.x * BN;
    int ty = tid / 16, tx = tid % 16;

    float s[8][8];   // master sums
    float y[8][8];   // chunk partial (starts at compensation term)
    #pragma unroll
    for (int i = 0; i < 8; i++)
        #pragma unroll
        for (int j = 0; j < 8; j++) { s[i][j] = 0.0f; y[i][j] = 0.0f; }

    // load mapping
    int a_row = tid >> 1;          // 0..127
    int a_k   = (tid & 1) * 8;     // 0 or 8  (two float4 at +0, +4)
    int b_k   = tid >> 4;          // 0..15
    int b_n   = (tid & 15) * 8;    // two float4 at +0, +4

    int gr = bm + a_row;
    bool a_ok = (gr < Mrows);
    const float* Aptr = A + (size_t)(a_ok ? gr : 0) * Kdim + a_k;
    const float* Bptr = B + (size_t)b_k * Ndim + bn + b_n;

    float4 pa0, pa1, pb0, pb1;

    // prologue: fetch tile 0
    if (a_ok) { pa0 = *(const float4*)(Aptr + 0); pa1 = *(const float4*)(Aptr + 4); }
    else      { pa0 = make_float4(0,0,0,0);       pa1 = make_float4(0,0,0,0); }
    pb0 = *(const float4*)(Bptr + 0);
    pb1 = *(const float4*)(Bptr + 4);

    int buf = 0;
    // store tile 0
    As[0][a_k + 0][a_row] = pa0.x; As[0][a_k + 1][a_row] = pa0.y;
    As[0][a_k + 2][a_row] = pa0.z; As[0][a_k + 3][a_row] = pa0.w;
    As[0][a_k + 4][a_row] = pa1.x; As[0][a_k + 5][a_row] = pa1.y;
    As[0][a_k + 6][a_row] = pa1.z; As[0][a_k + 7][a_row] = pa1.w;
    *(float4*)&Bs[0][b_k][b_n + 0] = pb0;
    *(float4*)&Bs[0][b_k][b_n + 4] = pb1;
    __syncthreads();

    int tile_cnt = 0;
    for (int k0 = BK; k0 <= Kdim; k0 += BK) {
        // prefetch next tile into registers (overlaps with compute below)
        if (k0 < Kdim) {
            if (a_ok) { pa0 = *(const float4*)(Aptr + k0 + 0); pa1 = *(const float4*)(Aptr + k0 + 4); }
            pb0 = *(const float4*)(Bptr + (size_t)k0 * Ndim + 0);
            pb1 = *(const float4*)(Bptr + (size_t)k0 * Ndim + 4);
        }

        // compute current chunk: plain FFMA chain into y
        #pragma unroll
        for (int k = 0; k < BK; k++) {
            float ar[8], br[8];
            const float4* ap = (const float4*)&As[buf][k][ty * 8];
            float4 A0 = ap[0], A1 = ap[1];
            ar[0]=A0.x; ar[1]=A0.y; ar[2]=A0.z; ar[3]=A0.w;
            ar[4]=A1.x; ar[5]=A1.y; ar[6]=A1.z; ar[7]=A1.w;
            const float4* bp = (const float4*)&Bs[buf][k][tx * 8];
            float4 B0 = bp[0], B1 = bp[1];
            br[0]=B0.x; br[1]=B0.y; br[2]=B0.z; br[3]=B0.w;
            br[4]=B1.x; br[5]=B1.y; br[6]=B1.z; br[7]=B1.w;

            #pragma unroll
            for (int i = 0; i < 8; i++)
                #pragma unroll
                for (int j = 0; j < 8; j++)
                    y[i][j] = __fmaf_rn(ar[i], br[j], y[i][j]);
        }

        // fold every FOLD_EVERY tiles: s += y exactly (error back into y)
        tile_cnt++;
        if ((tile_cnt & (FOLD_EVERY - 1)) == 0) {
            #pragma unroll
            for (int i = 0; i < 8; i++) {
                #pragma unroll
                for (int j = 0; j < 8; j++) {
                    float yo = y[i][j];
                    float t  = __fadd_rn(s[i][j], yo);
                    y[i][j]  = __fadd_rn(__fsub_rn(s[i][j], t), yo);
                    s[i][j]  = t;
                }
            }
        }

        // store prefetched tile into the other buffer
        if (k0 < Kdim) {
            int nb = buf ^ 1;
            As[nb][a_k + 0][a_row] = pa0.x; As[nb][a_k + 1][a_row] = pa0.y;
            As[nb][a_k + 2][a_row] = pa0.z; As[nb][a_k + 3][a_row] = pa0.w;
            As[nb][a_k + 4][a_row] = pa1.x; As[nb][a_k + 5][a_row] = pa1.y;
            As[nb][a_k + 6][a_row] = pa1.z; As[nb][a_k + 7][a_row] = pa1.w;
            *(float4*)&Bs[nb][b_k][b_n + 0] = pb0;
            *(float4*)&Bs[nb][b_k][b_n + 4] = pb1;
            __syncthreads();
            buf = nb;
        }
    }

    #pragma unroll
    for (int i = 0; i < 8; i++) {
        int r = bm + ty * 8 + i;
        if (r >= Mrows) continue;
        #pragma unroll
        for (int j = 0; j < 8; j++) {
            int ccol = bn + tx * 8 + j;
            // include residual y before bias for a tad more accuracy
            float v = __fadd_rn(__fadd_rn(s[i][j], y[i][j]), bias[ccol]);
            if (RELU) v = fmaxf(v, 0.0f);
            Cmat[(size_t)r * Ndim + ccol] = v;
        }
    }
}

// ---------------- heads: cls/box projections + softmax + deltas + clip ------
// fp64 accumulation for the 6 small dots (exact ordering-insensitive logits).
__global__ void heads_kernel(const float* __restrict__ Y2,
                             const float* __restrict__ Wc, const float* __restrict__ bc,
                             const float* __restrict__ Wb, const float* __restrict__ bb,
                             const float* __restrict__ props,
                             const int* __restrict__ isz,
                             float* __restrict__ scores, float* __restrict__ pboxes)
{
    int box = blockIdx.x;
    const float* x = Y2 + (size_t)box * FCD;

    double a0 = 0., a1 = 0., a2 = 0., a3 = 0., a4 = 0., a5 = 0.;
    for (int k = threadIdx.x; k < FCD; k += blockDim.x) {
        double xv = (double)x[k];
        a0 += xv * (double)Wc[k * 2 + 0];
        a1 += xv * (double)Wc[k * 2 + 1];
        a2 += xv * (double)Wb[k * 4 + 0];
        a3 += xv * (double)Wb[k * 4 + 1];
        a4 += xv * (double)Wb[k * 4 + 2];
        a5 += xv * (double)Wb[k * 4 + 3];
    }
    __shared__ double red[6][128];
    red[0][threadIdx.x] = a0; red[1][threadIdx.x] = a1; red[2][threadIdx.x] = a2;
    red[3][threadIdx.x] = a3; red[4][threadIdx.x] = a4; red[5][threadIdx.x] = a5;
    __syncthreads();
    for (int s = 64; s > 0; s >>= 1) {
        if (threadIdx.x < s)
            #pragma unroll
            for (int j = 0; j < 6; j++)
                red[j][threadIdx.x] += red[j][threadIdx.x + s];
        __syncthreads();
    }
    if (threadIdx.x == 0) {
        float l0 = (float)(red[0][0] + (double)bc[0]);
        float l1 = (float)(red[1][0] + (double)bc[1]);
        float m = fmaxf(l0, l1);
        float e0 = expf(__fsub_rn(l0, m)), e1 = expf(__fsub_rn(l1, m));
        scores[box] = __fdiv_rn(e1, __fadd_rn(e0, e1));

        float dx = (float)(red[2][0] + (double)bb[0]);
        float dy = (float)(red[3][0] + (double)bb[1]);
        float dw = fminf((float)(red[4][0] + (double)bb[2]), SCALE_CLAMP);
        float dh = fminf((float)(red[5][0] + (double)bb[3]), SCALE_CLAMP);

        const float* pr = props + (size_t)box * 4;
        float w = __fsub_rn(pr[2], pr[0]), h = __fsub_rn(pr[3], pr[1]);
        float cx = __fadd_rn(pr[0], __fmul_rn(0.5f, w));
        float cy = __fadd_rn(pr[1], __fmul_rn(0.5f, h));
        float pcx = __fadd_rn(__fmul_rn(dx, w), cx);
        float pcy = __fadd_rn(__fmul_rn(dy, h), cy);
        float pw = __fmul_rn(expf(dw), w);
        float ph = __fmul_rn(expf(dh), h);

        int img = box / MBOX;
        float Hh = (float)isz[img * 2 + 0];
        float Ww = (float)isz[img * 2 + 1];
        float bx1 = fminf(fmaxf(__fsub_rn(pcx, __fmul_rn(0.5f, pw)), 0.f), Ww);
        float by1 = fminf(fmaxf(__fsub_rn(pcy, __fmul_rn(0.5f, ph)), 0.f), Hh);
        float bx2 = fminf(fmaxf(__fadd_rn(pcx, __fmul_rn(0.5f, pw)), 0.f), Ww);
        float by2 = fminf(fmaxf(__fadd_rn(pcy, __fmul_rn(0.5f, ph)), 0.f), Hh);
        pboxes[box * 4 + 0] = bx1;
        pboxes[box * 4 + 1] = by1;
        pboxes[box * 4 + 2] = bx2;
        pboxes[box * 4 + 3] = by2;
    }
}

// ---------------- per-image stable sort + NMS + topk + write outputs --------
__global__ void __launch_bounds__(512) sortnms_kernel(
    const float* __restrict__ scores, const float* __restrict__ pboxes,
    float* __restrict__ out)
{
    int img = blockIdx.x;
    int tid = threadIdx.x;

    __shared__ float key[SORT_N];
    __shared__ int   idx[SORT_N];
    __shared__ float4 sb[MBOX];
    __shared__ float  sarea[MBOX];
    __shared__ unsigned long long keepw[NWORDS];

    for (int i = tid; i < SORT_N; i += 512) {
        if (i < MBOX) { key[i] = scores[img * MBOX + i]; idx[i] = i; }
        else          { key[i] = -FLT_MAX;               idx[i] = i; }
    }
    __syncthreads();

    // bitonic sort: descending score, tie-break ascending index (stable argsort)
    for (int k = 2; k <= SORT_N; k <<= 1) {
        for (int j = k >> 1; j > 0; j >>= 1) {
            for (int i = tid; i < SORT_N; i += 512) {
                int ixj = i ^ j;
                if (ixj > i) {
                    float ka = key[i], kb = key[ixj];
                    int ia = idx[i], ib = idx[ixj];
                    bool a_before_b = (ka > kb) || (ka == kb && ia < ib);
                    bool up = ((i & k) == 0);
                    bool sw = up ? !a_before_b : a_before_b;
                    if (sw) { key[i] = kb; key[ixj] = ka; idx[i] = ib; idx[ixj] = ia; }
                }
            }
            __syncthreads();
        }
    }

    // gather sorted boxes (already clipped)
    for (int i = tid; i < MBOX; i += 512) {
        const float* p = pboxes + (size_t)(img * MBOX + idx[i]) * 4;
        float4 b = make_float4(p[0], p[1], p[2], p[3]);
        sb[i] = b;
        sarea[i] = (b.z - b.x) * (b.w - b.y);
    }
    __syncthreads();

    // suppression bitmask: sup[i][w] bit jj set iff iou(i, w*64+jj) > T and j > i
    unsigned long long* sup = g_sup + (size_t)img * MBOX * NWORDS;
    for (int t = tid; t < MBOX * NWORDS; t += 512) {
        int i = t / NWORDS, w = t % NWORDS;
        float4 a = sb[i];
        float aa = sarea[i];
        unsigned long long m = 0ull;
        int j0 = w * 64;
        int jend = min(j0 + 64, MBOX);
        for (int j = max(j0, i + 1); j < jend; j++) {
            float4 b = sb[j];
            float lx = fmaxf(a.x, b.x), ly = fmaxf(a.y, b.y);
            float rx = fminf(a.z, b.z), ry = fminf(a.w, b.w);
            float iw = fmaxf(rx - lx, 0.f), ih = fmaxf(ry - ly, 0.f);
            float inter = iw * ih;
            float iou = inter / fmaxf(aa + sarea[j] - inter, 1e-9f);
            if (iou > NMS_THRESH) m |= 1ull << (j - j0);
        }
        sup[t] = m;
    }
    if (tid < NWORDS) {
        unsigned long long m = 0ull;
        for (int jj = 0; jj < 64; jj++) {
            int j = tid * 64 + jj;
            if (j < MBOX && key[j] > SCORE_THRESH) m |= 1ull << jj;
        }
        keepw[tid] = m;
    }
    __syncthreads();

    // sequential NMS scan (warp 0)
    if (tid < 32) {
        volatile unsigned long long* kw = keepw;
        for (int i = 0; i < MBOX; i++) {
            unsigned long long kwi = kw[i >> 6];
            __syncwarp();
            if ((kwi >> (i & 63)) & 1ull) {
                if (tid < NWORDS)
                    kw[tid] = kw[tid] & ~sup[(size_t)i * NWORDS + tid];
            }
            __syncwarp();
        }
        if (tid == 0) {
            int cnt = 0;
            for (int i = 0; i < MBOX; i++) {
                int w = i >> 6, b = i & 63;
                if ((kw[w] >> b) & 1ull) {
                    cnt++;
                    if (cnt > TOPK) kw[w] = kw[w] & ~(1ull << b);
                }
            }
        }
    }
    __syncthreads();

    // outputs: [boxes | scores | keep | order] all as float
    float* oB = out;
    float* oS = out + (size_t)NIMG * MBOX * 4;
    float* oK = oS + (size_t)NIMG * MBOX;
    float* oO = oK + (size_t)NIMG * MBOX;
    for (int i = tid; i < MBOX; i += 512) {
        float4 b = sb[i];
        size_t o = (size_t)(img * MBOX + i);
        oB[o * 4 + 0] = b.x;
        oB[o * 4 + 1] = b.y;
        oB[o * 4 + 2] = b.z;
        oB[o * 4 + 3] = b.w;
        oS[o] = key[i];
        int w = i >> 6, bb2 = i & 63;
        oK[o] = ((keepw[w] >> bb2) & 1ull) ? 1.0f : 0.0f;
        oO[o] = (float)idx[i];
    }
}

// ---------------- launcher ---------------------------------------------------
extern "C" void kernel_launch(void* const* d_in, const int* in_sizes, int n_in,
                              void* d_out, int out_size)
{
    const float* p2    = (const float*)d_in[0];
    const float* p3    = (const float*)d_in[1];
    const float* p4    = (const float*)d_in[2];
    const float* p5    = (const float*)d_in[3];
    const float* props = (const float*)d_in[4];
    const int*   isz   = (const int*)  d_in[5];
    const float* W1    = (const float*)d_in[6];
    const float* b1    = (const float*)d_in[7];
    const float* W2    = (const float*)d_in[8];
    const float* b2    = (const float*)d_in[9];
    const float* Wc    = (const float*)d_in[10];
    const float* bc    = (const float*)d_in[11];
    const float* Wb    = (const float*)d_in[12];
    const float* bb    = (const float*)d_in[13];
    float* out = (float*)d_out;

    void *pX, *pY1, *pY2, *pSc, *pPb;
    cudaGetSymbolAddress(&pX,  g_X);
    cudaGetSymbolAddress(&pY1, g_Y1);
    cudaGetSymbolAddress(&pY2, g_Y2);
    cudaGetSymbolAddress(&pSc, g_scores);
    cudaGetSymbolAddress(&pPb, g_pboxes);
    float* X  = (float*)pX;
    float* Y1 = (float*)pY1;
    float* Y2 = (float*)pY2;
    float* Sc = (float*)pSc;
    float* Pb = (float*)pPb;

    pool_kernel<<<NBOX, 256>>>(p2, p3, p4, p5, props);

    dim3 g1(FCD / 128, (NBOX + 127) / 128);
    sgemm_kernel<true><<<g1, 256>>>(X, W1, b1, Y1, NBOX, FCIN, FCD);
    sgemm_kernel<true><<<g1, 256>>>(Y1, W2, b2, Y2, NBOX, FCD, FCD);

    heads_kernel<<<NBOX, 128>>>(Y2, Wc, bc, Wb, bb, props, isz, Sc, Pb);

    sortnms_kernel<<<NIMG, 512>>>(Sc, Pb, out);
}

// round 8
// speedup vs baseline: 2.4182x; 1.0620x over previous
#include <cuda_runtime.h>
#include <math.h>
#include <float.h>
#include <stdint.h>

// Problem constants (fixed shapes from reference setup_inputs)
#define NIMG 2
#define MBOX 1000
#define NBOX (NIMG*MBOX)
#define CCH  256
#define RR   7
#define FCIN (CCH*RR*RR)      // 12544
#define FCD  1024
#define SORT_N 1024
#define NWORDS 16             // ceil(1000/64)
#define SCORE_THRESH 0.05f
#define NMS_THRESH 0.5f
#define TOPK 100
#define SCALE_CLAMP 4.135166556742356f  // log(1000/16)

// ---------------- scratch (device globals; no allocations allowed) ----------
__device__ float g_X [NBOX * FCIN];   // pooled features, row-major (2000 x 12544)
__device__ float g_Y1[NBOX * FCD];
__device__ float g_Y2[NBOX * FCD];
__device__ float g_scores[NBOX];
__device__ float g_pboxes[NBOX * 4];  // clipped predicted boxes
__device__ unsigned long long g_sup[NIMG * MBOX * NWORDS];

// ---------------- pooling (ROIAlign-nearest per reference) ------------------
__global__ void pool_kernel(const float* __restrict__ p2, const float* __restrict__ p3,
                            const float* __restrict__ p4, const float* __restrict__ p5,
                            const float* __restrict__ props)
{
    int box = blockIdx.x;           // 0..1999
    int img = box / MBOX;

    __shared__ int six[RR], siy[RR];
    __shared__ const float* sbase;
    __shared__ int sW, sHW;

    if (threadIdx.x == 0) {
        const float* fmaps[4] = {p2, p3, p4, p5};
        const int   Hs[4] = {200, 100, 50, 25};
        const int   Ws[4] = {304, 152, 76, 38};
        const float sc4[4] = {0.25f, 0.125f, 0.0625f, 0.03125f};

        const float* pr = props + (size_t)box * 4;
        float x1o = pr[0], y1o = pr[1], x2o = pr[2], y2o = pr[3];

        float w = __fsub_rn(x2o, x1o);
        float h = __fsub_rn(y2o, y1o);
        float s = sqrtf(fmaxf(__fmul_rn(w, h), 1e-6f));
        float lv = floorf(__fadd_rn(4.0f, log2f(__fadd_rn(__fdiv_rn(s, 224.0f), 1e-8f))));
        lv = fminf(fmaxf(lv, 2.0f), 5.0f);
        int lvl = (int)lv - 2;      // 0..3

        float sc = sc4[lvl];        // powers of two: multiply is exact
        float x1 = __fmul_rn(x1o, sc), y1 = __fmul_rn(y1o, sc);
        float x2 = __fmul_rn(x2o, sc), y2 = __fmul_rn(y2o, sc);
        float bw = __fdiv_rn(fmaxf(__fsub_rn(x2, x1), 1.0f), 7.0f);
        float bh = __fdiv_rn(fmaxf(__fsub_rn(y2, y1), 1.0f), 7.0f);
        int Wl = Ws[lvl], Hl = Hs[lvl];
        for (int j = 0; j < RR; j++) {
            float cs = (float)j + 0.5f;
            float gx = __fadd_rn(x1, __fmul_rn(cs, bw));
            float gy = __fadd_rn(y1, __fmul_rn(cs, bh));
            int ix = (int)gx;
            int iy = (int)gy;
            six[j] = min(max(ix, 0), Wl - 1);
            siy[j] = min(max(iy, 0), Hl - 1);
        }
        sbase = fmaps[lvl] + (size_t)img * CCH * Hl * Wl;
        sW = Wl;
        sHW = Hl * Wl;
    }
    __syncthreads();

    const float* base = sbase;
    int Wl = sW, HW = sHW;
    float* out = g_X + (size_t)box * FCIN;
    for (int t = threadIdx.x; t < FCIN; t += blockDim.x) {
        int c = t / 49;
        int p = t % 49;
        int gy = p / 7, gx = p % 7;
        out[t] = base[(size_t)c * HW + siy[gy] * Wl + six[gx]];
    }
}

// ---------------- tf32x3 tensor-core GEMM, chunk-compensated ----------------
// C = relu(A @ B + bias).  A: Mrows x Kdim row-major; B: Kdim x Ndim row-major.
// Kdim % 64 == 0, Ndim % 128 == 0.
// Each fp32 operand is split hi = tf32(x), lo = tf32(x - hi); products via
// 3 mma.m16n8k8: hi*hi + hi*lo + lo*hi  (per-product rel err ~6e-7).
// MMA accumulators hold the 64-k chunk partial (seeded with the fast2sum
// compensation); folded into master fp32 sums every CH=8 tiles, so all
// accumulator roundings happen at chunk magnitude.
__device__ __forceinline__ uint32_t f2tf(float v) {
    uint32_t r;
    asm("cvt.rna.tf32.f32 %0, %1;" : "=r"(r) : "f"(v));
    return r;
}
__device__ __forceinline__ void mma_tf32(float* c, const uint32_t* a,
                                         uint32_t b0, uint32_t b1) {
    asm volatile(
        "mma.sync.aligned.m16n8k8.row.col.f32.tf32.tf32.f32 "
        "{%0,%1,%2,%3},{%4,%5,%6,%7},{%8,%9},{%0,%1,%2,%3};\n"
        : "+f"(c[0]), "+f"(c[1]), "+f"(c[2]), "+f"(c[3])
        : "r"(a[0]), "r"(a[1]), "r"(a[2]), "r"(a[3]), "r"(b0), "r"(b1));
}

template<bool RELU>
__global__ void __launch_bounds__(256) tcgemm_kernel(
    const float* __restrict__ A, const float* __restrict__ B,
    const float* __restrict__ bias, float* __restrict__ Cmat,
    int Mrows, int Kdim, int Ndim)
{
    const int BM = 128, BN = 128, BK = 8;
    const int CH = 8;   // fold every 8 tiles = 64 k
    // smem: [k][m or n] with row stride 132 (bank-conflict-free frag loads)
    __shared__ float Ah[2][BK][132], Al[2][BK][132];
    __shared__ float Bh[2][BK][132], Bl[2][BK][132];

    int tid = threadIdx.x;
    int lane = tid & 31, wid = tid >> 5;
    int g = lane >> 2, tig = lane & 3;
    int warp_m = (wid & 3) * 32;     // 4 warps cover 128 m
    int warp_n = (wid >> 2) * 64;    // 2 warps cover 128 n
    int bm = blockIdx.y * BM, bn = blockIdx.x * BN;

    float s[2][8][4];   // master sums
    float c[2][8][4];   // chunk partial (mma accumulator; seeded with comp)
    #pragma unroll
    for (int mt = 0; mt < 2; mt++)
        #pragma unroll
        for (int nt = 0; nt < 8; nt++)
            #pragma unroll
            for (int q = 0; q < 4; q++) { s[mt][nt][q] = 0.f; c[mt][nt][q] = 0.f; }

    // fill mapping: A tile 128m x 8k, B tile 8k x 128n; one float4 each/thread
    int am = tid >> 1, ak = (tid & 1) * 4;
    int bk = tid >> 5, bn4 = (tid & 31) * 4;
    int gr = bm + am;
    bool a_ok = (gr < Mrows);
    const float* Aptr = A + (size_t)(a_ok ? gr : 0) * Kdim + ak;
    const float* Bptr = B + (size_t)bk * Ndim + bn + bn4;

    float4 av = make_float4(0.f, 0.f, 0.f, 0.f), bv;
    if (a_ok) av = *(const float4*)(Aptr);
    bv = *(const float4*)(Bptr);

    // store tile 0 (split into hi/lo tf32 bit patterns held as floats)
    {
        float va[4] = {av.x, av.y, av.z, av.w};
        float vb[4] = {bv.x, bv.y, bv.z, bv.w};
        #pragma unroll
        for (int j = 0; j < 4; j++) {
            float hf = __uint_as_float(f2tf(va[j]));
            Ah[0][ak + j][am] = hf;
            Al[0][ak + j][am] = __uint_as_float(f2tf(__fsub_rn(va[j], hf)));
            float hg = __uint_as_float(f2tf(vb[j]));
            Bh[0][bk][bn4 + j] = hg;
            Bl[0][bk][bn4 + j] = __uint_as_float(f2tf(__fsub_rn(vb[j], hg)));
        }
    }
    __syncthreads();

    int buf = 0, tile = 0;
    for (int k0 = BK; k0 <= Kdim; k0 += BK) {
        // prefetch next tile into registers
        if (k0 < Kdim) {
            if (a_ok) av = *(const float4*)(Aptr + k0);
            bv = *(const float4*)(Bptr + (size_t)k0 * Ndim);
        }

        // ---- compute current tile (one k8 step) ----
        uint32_t aH[2][4], aL[2][4];
        #pragma unroll
        for (int mt = 0; mt < 2; mt++) {
            int r0 = warp_m + mt * 16 + g;
            aH[mt][0] = __float_as_uint(Ah[buf][tig    ][r0    ]);
            aH[mt][1] = __float_as_uint(Ah[buf][tig    ][r0 + 8]);
            aH[mt][2] = __float_as_uint(Ah[buf][tig + 4][r0    ]);
            aH[mt][3] = __float_as_uint(Ah[buf][tig + 4][r0 + 8]);
            aL[mt][0] = __float_as_uint(Al[buf][tig    ][r0    ]);
            aL[mt][1] = __float_as_uint(Al[buf][tig    ][r0 + 8]);
            aL[mt][2] = __float_as_uint(Al[buf][tig + 4][r0    ]);
            aL[mt][3] = __float_as_uint(Al[buf][tig + 4][r0 + 8]);
        }
        #pragma unroll
        for (int nt = 0; nt < 8; nt++) {
            int nn = warp_n + nt * 8 + g;
            uint32_t b0h = __float_as_uint(Bh[buf][tig    ][nn]);
            uint32_t b1h = __float_as_uint(Bh[buf][tig + 4][nn]);
            uint32_t b0l = __float_as_uint(Bl[buf][tig    ][nn]);
            uint32_t b1l = __float_as_uint(Bl[buf][tig + 4][nn]);
            #pragma unroll
            for (int mt = 0; mt < 2; mt++) {
                mma_tf32(c[mt][nt], aH[mt], b0h, b1h);   // hi*hi
                mma_tf32(c[mt][nt], aH[mt], b0l, b1l);   // hi*lo
                mma_tf32(c[mt][nt], aL[mt], b0h, b1h);   // lo*hi
            }
        }

        // ---- fold chunk into master sums every CH tiles (fast2sum) ----
        tile++;
        if ((tile & (CH - 1)) == 0) {
            #pragma unroll
            for (int mt = 0; mt < 2; mt++)
                #pragma unroll
                for (int nt = 0; nt < 8; nt++)
                    #pragma unroll
                    for (int q = 0; q < 4; q++) {
                        float yo = c[mt][nt][q];
                        float t  = __fadd_rn(s[mt][nt][q], yo);
                        c[mt][nt][q] = __fadd_rn(__fsub_rn(s[mt][nt][q], t), yo);
                        s[mt][nt][q] = t;
                    }
        }

        // ---- store prefetched tile into other buffer ----
        if (k0 < Kdim) {
            int nb = buf ^ 1;
            float va[4] = {av.x, av.y, av.z, av.w};
            float vb2[4] = {bv.x, bv.y, bv.z, bv.w};
            #pragma unroll
            for (int j = 0; j < 4; j++) {
                float hf = __uint_as_float(f2tf(va[j]));
                Ah[nb][ak + j][am] = hf;
                Al[nb][ak + j][am] = __uint_as_float(f2tf(__fsub_rn(va[j], hf)));
                float hg = __uint_as_float(f2tf(vb2[j]));
                Bh[nb][bk][bn4 + j] = hg;
                Bl[nb][bk][bn4 + j] = __uint_as_float(f2tf(__fsub_rn(vb2[j], hg)));
            }
            __syncthreads();
            buf = nb;
        }
    }

    // ---- epilogue: C-fragment mapping: rows g / g+8, cols 2*tig, 2*tig+1 ----
    #pragma unroll
    for (int mt = 0; mt < 2; mt++) {
        int r0 = bm + warp_m + mt * 16 + g;
        #pragma unroll
        for (int nt = 0; nt < 8; nt++) {
            int col = bn + warp_n + nt * 8 + tig * 2;
            if (r0 < Mrows) {
                float v0 = __fadd_rn(__fadd_rn(s[mt][nt][0], c[mt][nt][0]), bias[col]);
                float v1 = __fadd_rn(__fadd_rn(s[mt][nt][1], c[mt][nt][1]), bias[col + 1]);
                if (RELU) { v0 = fmaxf(v0, 0.f); v1 = fmaxf(v1, 0.f); }
                *(float2*)(Cmat + (size_t)r0 * Ndim + col) = make_float2(v0, v1);
            }
            if (r0 + 8 < Mrows) {
                float v2 = __fadd_rn(__fadd_rn(s[mt][nt][2], c[mt][nt][2]), bias[col]);
                float v3 = __fadd_rn(__fadd_rn(s[mt][nt][3], c[mt][nt][3]), bias[col + 1]);
                if (RELU) { v2 = fmaxf(v2, 0.f); v3 = fmaxf(v3, 0.f); }
                *(float2*)(Cmat + (size_t)(r0 + 8) * Ndim + col) = make_float2(v2, v3);
            }
        }
    }
}

// ---------------- heads: cls/box projections + softmax + deltas + clip ------
// fp64 accumulation for the 6 small dots (exact ordering-insensitive logits).
__global__ void heads_kernel(const float* __restrict__ Y2,
                             const float* __restrict__ Wc, const float* __restrict__ bc,
                             const float* __restrict__ Wb, const float* __restrict__ bb,
                             const float* __restrict__ props,
                             const int* __restrict__ isz,
                             float* __restrict__ scores, float* __restrict__ pboxes)
{
    int box = blockIdx.x;
    const float* x = Y2 + (size_t)box * FCD;

    double a0 = 0., a1 = 0., a2 = 0., a3 = 0., a4 = 0., a5 = 0.;
    for (int k = threadIdx.x; k < FCD; k += blockDim.x) {
        double xv = (double)x[k];
        a0 += xv * (double)Wc[k * 2 + 0];
        a1 += xv * (double)Wc[k * 2 + 1];
        a2 += xv * (double)Wb[k * 4 + 0];
        a3 += xv * (double)Wb[k * 4 + 1];
        a4 += xv * (double)Wb[k * 4 + 2];
        a5 += xv * (double)Wb[k * 4 + 3];
    }
    __shared__ double red[6][128];
    red[0][threadIdx.x] = a0; red[1][threadIdx.x] = a1; red[2][threadIdx.x] = a2;
    red[3][threadIdx.x] = a3; red[4][threadIdx.x] = a4; red[5][threadIdx.x] = a5;
    __syncthreads();
    for (int s = 64; s > 0; s >>= 1) {
        if (threadIdx.x < s)
            #pragma unroll
            for (int j = 0; j < 6; j++)
                red[j][threadIdx.x] += red[j][threadIdx.x + s];
        __syncthreads();
    }
    if (threadIdx.x == 0) {
        float l0 = (float)(red[0][0] + (double)bc[0]);
        float l1 = (float)(red[1][0] + (double)bc[1]);
        float m = fmaxf(l0, l1);
        float e0 = expf(__fsub_rn(l0, m)), e1 = expf(__fsub_rn(l1, m));
        scores[box] = __fdiv_rn(e1, __fadd_rn(e0, e1));

        float dx = (float)(red[2][0] + (double)bb[0]);
        float dy = (float)(red[3][0] + (double)bb[1]);
        float dw = fminf((float)(red[4][0] + (double)bb[2]), SCALE_CLAMP);
        float dh = fminf((float)(red[5][0] + (double)bb[3]), SCALE_CLAMP);

        const float* pr = props + (size_t)box * 4;
        float w = __fsub_rn(pr[2], pr[0]), h = __fsub_rn(pr[3], pr[1]);
        float cx = __fadd_rn(pr[0], __fmul_rn(0.5f, w));
        float cy = __fadd_rn(pr[1], __fmul_rn(0.5f, h));
        float pcx = __fadd_rn(__fmul_rn(dx, w), cx);
        float pcy = __fadd_rn(__fmul_rn(dy, h), cy);
        float pw = __fmul_rn(expf(dw), w);
        float ph = __fmul_rn(expf(dh), h);

        int img = box / MBOX;
        float Hh = (float)isz[img * 2 + 0];
        float Ww = (float)isz[img * 2 + 1];
        float bx1 = fminf(fmaxf(__fsub_rn(pcx, __fmul_rn(0.5f, pw)), 0.f), Ww);
        float by1 = fminf(fmaxf(__fsub_rn(pcy, __fmul_rn(0.5f, ph)), 0.f), Hh);
        float bx2 = fminf(fmaxf(__fadd_rn(pcx, __fmul_rn(0.5f, pw)), 0.f), Ww);
        float by2 = fminf(fmaxf(__fadd_rn(pcy, __fmul_rn(0.5f, ph)), 0.f), Hh);
        pboxes[box * 4 + 0] = bx1;
        pboxes[box * 4 + 1] = by1;
        pboxes[box * 4 + 2] = bx2;
        pboxes[box * 4 + 3] = by2;
    }
}

// ---------------- per-image stable sort + NMS + topk + write outputs --------
__global__ void __launch_bounds__(512) sortnms_kernel(
    const float* __restrict__ scores, const float* __restrict__ pboxes,
    float* __restrict__ out)
{
    int img = blockIdx.x;
    int tid = threadIdx.x;

    __shared__ float key[SORT_N];
    __shared__ int   idx[SORT_N];
    __shared__ float4 sb[MBOX];
    __shared__ float  sarea[MBOX];
    __shared__ unsigned long long keepw[NWORDS];

    for (int i = tid; i < SORT_N; i += 512) {
        if (i < MBOX) { key[i] = scores[img * MBOX + i]; idx[i] = i; }
        else          { key[i] = -FLT_MAX;               idx[i] = i; }
    }
    __syncthreads();

    // bitonic sort: descending score, tie-break ascending index (stable argsort)
    for (int k = 2; k <= SORT_N; k <<= 1) {
        for (int j = k >> 1; j > 0; j >>= 1) {
            for (int i = tid; i < SORT_N; i += 512) {
                int ixj = i ^ j;
                if (ixj > i) {
                    float ka = key[i], kb = key[ixj];
                    int ia = idx[i], ib = idx[ixj];
                    bool a_before_b = (ka > kb) || (ka == kb && ia < ib);
                    bool up = ((i & k) == 0);
                    bool sw = up ? !a_before_b : a_before_b;
                    if (sw) { key[i] = kb; key[ixj] = ka; idx[i] = ib; idx[ixj] = ia; }
                }
            }
            __syncthreads();
        }
    }

    // gather sorted boxes (already clipped)
    for (int i = tid; i < MBOX; i += 512) {
        const float* p = pboxes + (size_t)(img * MBOX + idx[i]) * 4;
        float4 b = make_float4(p[0], p[1], p[2], p[3]);
        sb[i] = b;
        sarea[i] = (b.z - b.x) * (b.w - b.y);
    }
    __syncthreads();

    // suppression bitmask: sup[i][w] bit jj set iff iou(i, w*64+jj) > T and j > i
    unsigned long long* sup = g_sup + (size_t)img * MBOX * NWORDS;
    for (int t = tid; t < MBOX * NWORDS; t += 512) {
        int i = t / NWORDS, w = t % NWORDS;
        float4 a = sb[i];
        float aa = sarea[i];
        unsigned long long m = 0ull;
        int j0 = w * 64;
        int jend = min(j0 + 64, MBOX);
        for (int j = max(j0, i + 1); j < jend; j++) {
            float4 b = sb[j];
            float lx = fmaxf(a.x, b.x), ly = fmaxf(a.y, b.y);
            float rx = fminf(a.z, b.z), ry = fminf(a.w, b.w);
            float iw = fmaxf(rx - lx, 0.f), ih = fmaxf(ry - ly, 0.f);
            float inter = iw * ih;
            float iou = inter / fmaxf(aa + sarea[j] - inter, 1e-9f);
            if (iou > NMS_THRESH) m |= 1ull << (j - j0);
        }
        sup[t] = m;
    }
    if (tid < NWORDS) {
        unsigned long long m = 0ull;
        for (int jj = 0; jj < 64; jj++) {
            int j = tid * 64 + jj;
            if (j < MBOX && key[j] > SCORE_THRESH) m |= 1ull << jj;
        }
        keepw[tid] = m;
    }
    __syncthreads();

    // sequential NMS scan (warp 0)
    if (tid < 32) {
        volatile unsigned long long* kw = keepw;
        for (int i = 0; i < MBOX; i++) {
            unsigned long long kwi = kw[i >> 6];
            __syncwarp();
            if ((kwi >> (i & 63)) & 1ull) {
                if (tid < NWORDS)
                    kw[tid] = kw[tid] & ~sup[(size_t)i * NWORDS + tid];
            }
            __syncwarp();
        }
        if (tid == 0) {
            int cnt = 0;
            for (int i = 0; i < MBOX; i++) {
                int w = i >> 6, b = i & 63;
                if ((kw[w] >> b) & 1ull) {
                    cnt++;
                    if (cnt > TOPK) kw[w] = kw[w] & ~(1ull << b);
                }
            }
        }
    }
    __syncthreads();

    // outputs: [boxes | scores | keep | order] all as float
    float* oB = out;
    float* oS = out + (size_t)NIMG * MBOX * 4;
    float* oK = oS + (size_t)NIMG * MBOX;
    float* oO = oK + (size_t)NIMG * MBOX;
    for (int i = tid; i < MBOX; i += 512) {
        float4 b = sb[i];
        size_t o = (size_t)(img * MBOX + i);
        oB[o * 4 + 0] = b.x;
        oB[o * 4 + 1] = b.y;
        oB[o * 4 + 2] = b.z;
        oB[o * 4 + 3] = b.w;
        oS[o] = key[i];
        int w = i >> 6, bb2 = i & 63;
        oK[o] = ((keepw[w] >> bb2) & 1ull) ? 1.0f : 0.0f;
        oO[o] = (float)idx[i];
    }
}

// ---------------- launcher ---------------------------------------------------
extern "C" void kernel_launch(void* const* d_in, const int* in_sizes, int n_in,
                              void* d_out, int out_size)
{
    const float* p2    = (const float*)d_in[0];
    const float* p3    = (const float*)d_in[1];
    const float* p4    = (const float*)d_in[2];
    const float* p5    = (const float*)d_in[3];
    const float* props = (const float*)d_in[4];
    const int*   isz   = (const int*)  d_in[5];
    const float* W1    = (const float*)d_in[6];
    const float* b1    = (const float*)d_in[7];
    const float* W2    = (const float*)d_in[8];
    const float* b2    = (const float*)d_in[9];
    const float* Wc    = (const float*)d_in[10];
    const float* bc    = (const float*)d_in[11];
    const float* Wb    = (const float*)d_in[12];
    const float* bb    = (const float*)d_in[13];
    float* out = (float*)d_out;

    void *pX, *pY1, *pY2, *pSc, *pPb;
    cudaGetSymbolAddress(&pX,  g_X);
    cudaGetSymbolAddress(&pY1, g_Y1);
    cudaGetSymbolAddress(&pY2, g_Y2);
    cudaGetSymbolAddress(&pSc, g_scores);
    cudaGetSymbolAddress(&pPb, g_pboxes);
    float* X  = (float*)pX;
    float* Y1 = (float*)pY1;
    float* Y2 = (float*)pY2;
    float* Sc = (float*)pSc;
    float* Pb = (float*)pPb;

    pool_kernel<<<NBOX, 256>>>(p2, p3, p4, p5, props);

    dim3 g1(FCD / 128, (NBOX + 127) / 128);
    tcgemm_kernel<true><<<g1, 256>>>(X, W1, b1, Y1, NBOX, FCIN, FCD);
    tcgemm_kernel<true><<<g1, 256>>>(Y1, W2, b2, Y2, NBOX, FCD, FCD);

    heads_kernel<<<NBOX, 128>>>(Y2, Wc, bc, Wb, bb, props, isz, Sc, Pb);

    sortnms_kernel<<<NIMG, 512>>>(Sc, Pb, out);
}